// round 14
// baseline (speedup 1.0000x reference)
#include <cuda_runtime.h>
#include <cuda_bf16.h>
#include <math.h>
#include <stdint.h>

// ---------------------------------------------------------------------------
// Problem constants
// ---------------------------------------------------------------------------
#define BB    16
#define CHN   16
#define HZ    128
#define HX    256
#define EMB   384
#define NHD   6
#define NGRP  5
#define NTZ   64
#define NTX   256
#define GBN   80
#define NTOT  320
#define MTOT  25600    // GBN * NTOT

#define OFF_OUT  0
#define OFF_ZF   1966080
#define OFF_XF   6160384
#define OFF_ZCG  22937600
#define OFF_XCG  27131904
#define OFF_OV   43909120
#define OFF_OI   43909376

// ---------------------------------------------------------------------------
// Device scratch
// ---------------------------------------------------------------------------
__device__ float g_conv18[16*16*14*14];
__device__ float g_conv16[16*16*16*16];
__device__ float g_conv14[16*16*18*18];
__device__ float g_wbuf[256];
__device__ int   g_order[256];
__device__ float g_t[25600*384];        // unified token buffer (concat layout)
__device__ float g_h[25600*384];
__device__ float g_qkv[25600*1152];
__device__ float g_o[25600*384];
__device__ float g_hidden[25600*1536];
__device__ float g_col[25600*768];
__device__ float g_patchw_t[768*384];

// ---------------------------------------------------------------------------
// PTX helpers
// ---------------------------------------------------------------------------
__device__ __forceinline__ void mma1688_tf32(float* d, const uint32_t* a, const uint32_t* b) {
    asm volatile("mma.sync.aligned.m16n8k8.row.col.f32.tf32.tf32.f32 "
        "{%0,%1,%2,%3},{%4,%5,%6,%7},{%8,%9},{%0,%1,%2,%3};"
        : "+f"(d[0]),"+f"(d[1]),"+f"(d[2]),"+f"(d[3])
        : "r"(a[0]),"r"(a[1]),"r"(a[2]),"r"(a[3]), "r"(b[0]),"r"(b[1]));
}
__device__ __forceinline__ void cp16(void* dst_smem, const void* src) {
    uint32_t d = (uint32_t)__cvta_generic_to_shared(dst_smem);
    asm volatile("cp.async.cg.shared.global [%0],[%1],16;" :: "r"(d), "l"(src));
}
__device__ __forceinline__ void ldsm4(uint32_t* d, uint32_t a) {
    asm volatile("ldmatrix.sync.aligned.m8n8.x4.shared.b16 {%0,%1,%2,%3},[%4];"
        : "=r"(d[0]),"=r"(d[1]),"=r"(d[2]),"=r"(d[3]) : "r"(a));
}
__device__ __forceinline__ uint32_t f2tfr(float f) {
    uint32_t u;
    asm("cvt.rna.tf32.f32 %0, %1;" : "=r"(u) : "f"(f));
    return u;
}
__device__ __forceinline__ float tf32r(float f) {
    return __uint_as_float(f2tfr(f));
}

__device__ __forceinline__ float gelu_f(float x)
{
    float x3 = x*x*x;
    return 0.5f*x*(1.0f + tanhf(0.7978845608028654f*(x + 0.044715f*x3)));
}

// ---------------------------------------------------------------------------
// TF32 tensor-core GEMM, latency-optimized: CTA 128x64x32, 8 warps (4Mx2N),
// warp tile 32x32, 2-stage cp.async, 3 CTAs/SM (24 warps) for latency hiding.
// EPI: 0 none, 1 +bias, 2 gelu, 3 +residual, 4 +residual +pos
// requires M%128==0, N%64==0, K%32==0
// ---------------------------------------------------------------------------
#define AS_W   36
#define BS_W   72
#define AS_TILE (128*AS_W)
#define BS_TILE (32*BS_W)
#define GEMM_SMEM_BYTES ((2*AS_TILE + 2*BS_TILE)*4)

template<int EPI>
__global__ void __launch_bounds__(256,3) gemm_tf32_kernel(
    const float* __restrict__ A, const float* __restrict__ B,
    const float* __restrict__ aux, float* __restrict__ C,
    int M, int N, int K,
    const float* __restrict__ pz, const float* __restrict__ px)
{
    extern __shared__ uint32_t sm_[];
    uint32_t* AsBase = sm_;
    uint32_t* BsBase = sm_ + 2*AS_TILE;

    const int tid  = threadIdx.x;
    const int warp = tid >> 5, lane = tid & 31;
    const int wm = (warp & 3) * 32;
    const int wn = (warp >> 2) * 32;
    const int mBase = blockIdx.y * 128, nBase = blockIdx.x * 64;
    const int gid = lane >> 2, tg = lane & 3;
    const int KT = K >> 5;

    // A: 128x32 -> 1024 float4 chunks, 4/thread; B: 32x64 -> 512, 2/thread
    int arow[4], acof[4], bkr[2], bnc[2];
    #pragma unroll
    for (int c = 0; c < 4; c++) {
        int ch = tid + c*256;
        arow[c] = ch >> 3;  acof[c] = (ch & 7) * 4;
    }
    #pragma unroll
    for (int c = 0; c < 2; c++) {
        int ch = tid + c*256;
        bkr[c]  = ch >> 4;  bnc[c]  = (ch & 15) * 4;
    }

    const int lmRow = wm + (lane & 15);
    const int lmCol = (lane >> 4) * 4;
    uint32_t aAddrStage[2];
    #pragma unroll
    for (int st = 0; st < 2; st++)
        aAddrStage[st] = (uint32_t)__cvta_generic_to_shared(
            AsBase + st*AS_TILE + lmRow*AS_W + lmCol);

    float acc[2][4][4];
    #pragma unroll
    for (int i = 0; i < 2; i++)
        #pragma unroll
        for (int j = 0; j < 4; j++)
            #pragma unroll
            for (int e = 0; e < 4; e++) acc[i][j][e] = 0.f;

    auto issue = [&](int kt, int buf) {
        int k0 = kt * 32;
        uint32_t* as = AsBase + buf*AS_TILE;
        uint32_t* bs = BsBase + buf*BS_TILE;
        #pragma unroll
        for (int c = 0; c < 4; c++)
            cp16(as + arow[c]*AS_W + acof[c],
                 A + (size_t)(mBase + arow[c])*K + k0 + acof[c]);
        #pragma unroll
        for (int c = 0; c < 2; c++)
            cp16(bs + bkr[c]*BS_W + bnc[c],
                 B + (size_t)(k0 + bkr[c])*N + nBase + bnc[c]);
        asm volatile("cp.async.commit_group;");
    };

    issue(0, 0);

    for (int kt = 0; kt < KT; kt++) {
        if (kt + 1 < KT) {
            issue(kt + 1, (kt + 1) & 1);
            asm volatile("cp.async.wait_group 1;");
        } else {
            asm volatile("cp.async.wait_group 0;");
        }
        __syncthreads();

        const int stg = kt & 1;
        const uint32_t aAddr = aAddrStage[stg];
        const uint32_t* bs = BsBase + stg*BS_TILE;
        #pragma unroll
        for (int ks = 0; ks < 32; ks += 8) {
            uint32_t a[2][4], b[4][2];
            #pragma unroll
            for (int mt = 0; mt < 2; mt++)
                ldsm4(a[mt], aAddr + (mt*16*AS_W + ks)*4);
            #pragma unroll
            for (int nt = 0; nt < 4; nt++) {
                b[nt][0] = bs[(ks + tg    )*BS_W + wn + nt*8 + gid];
                b[nt][1] = bs[(ks + tg + 4)*BS_W + wn + nt*8 + gid];
            }
            #pragma unroll
            for (int mt = 0; mt < 2; mt++)
                #pragma unroll
                for (int nt = 0; nt < 4; nt++)
                    mma1688_tf32(acc[mt][nt], a[mt], b[nt]);
        }
        __syncthreads();
    }

    #pragma unroll
    for (int mt = 0; mt < 2; mt++) {
        #pragma unroll
        for (int nt = 0; nt < 4; nt++) {
            #pragma unroll
            for (int half = 0; half < 2; half++) {
                int m = mBase + wm + mt*16 + gid + half*8;
                int n = nBase + wn + nt*8 + tg*2;
                float v0 = acc[mt][nt][half*2];
                float v1 = acc[mt][nt][half*2+1];
                if (EPI == 1) { v0 += aux[n]; v1 += aux[n+1]; }
                else if (EPI == 2) { v0 = gelu_f(v0); v1 = gelu_f(v1); }
                else if (EPI == 3) {
                    const float2 rr = *(const float2*)(aux + (size_t)m*N + n);
                    v0 += rr.x; v1 += rr.y;
                } else if (EPI == 4) {
                    const float2 rr = *(const float2*)(aux + (size_t)m*N + n);
                    v0 += rr.x; v1 += rr.y;
                    int ntok = m % NTOT;
                    const float* pp = (ntok < NTZ)
                        ? (pz + (size_t)ntok*384 + n)
                        : (px + (size_t)(ntok-NTZ)*384 + n);
                    v0 += pp[0]; v1 += pp[1];
                }
                *(float2*)(C + (size_t)m*N + n) = make_float2(v0, v1);
            }
        }
    }
}

// ---------------------------------------------------------------------------
// Tensor-core flash attention (tf32 mma, online softmax) — unchanged
// ---------------------------------------------------------------------------
template<int N>
__global__ void __launch_bounds__(256) attn_mma_kernel(
    const float* __restrict__ qkv, float* __restrict__ o, int rowOff)
{
    extern __shared__ float smf[];
    float* Ks = smf;                          // N*68
    float* Vt = smf + N*68;                   // 64*(N+4)
    float* Ps = smf + N*68 + 64*(N+4);        // 8 * 16*20

    const int gb = blockIdx.x / NHD, h = blockIdx.x % NHD;
    const int tid = threadIdx.x;
    const size_t base = (size_t)gb * NTOT + rowOff;
    const int VLD = N + 4;

    for (int idx = tid; idx < N*64; idx += 256) {
        int n = idx >> 6, d = idx & 63;
        const float* p = qkv + (base + n)*1152 + h*64 + d;
        Ks[n*68 + d]   = tf32r(p[384]);
        Vt[d*VLD + n]  = tf32r(p[768]);
    }
    __syncthreads();

    const int warp = tid >> 5, lane = tid & 31;
    const int gid = lane >> 2, tg = lane & 3;
    float* Pw = Ps + warp * (16*20);
    constexpr int NT = N / 16;

    for (int mt = warp; mt < NT; mt += 8) {
        int m0 = mt * 16;
        uint32_t aq[8][4];
        const float* q0 = qkv + (base + m0 + gid)*1152 + h*64;
        const float* q1 = q0 + 8*1152;
        #pragma unroll
        for (int c = 0; c < 8; c++) {
            aq[c][0] = f2tfr(q0[c*8 + tg]     * 0.125f);
            aq[c][1] = f2tfr(q1[c*8 + tg]     * 0.125f);
            aq[c][2] = f2tfr(q0[c*8 + tg + 4] * 0.125f);
            aq[c][3] = f2tfr(q1[c*8 + tg + 4] * 0.125f);
        }

        float o_[8][4];
        #pragma unroll
        for (int j = 0; j < 8; j++)
            #pragma unroll
            for (int e = 0; e < 4; e++) o_[j][e] = 0.f;
        float mx0 = -1e30f, mx1 = -1e30f, l0 = 0.f, l1 = 0.f;

        for (int n0 = 0; n0 < N; n0 += 16) {
            float s[2][4];
            #pragma unroll
            for (int j = 0; j < 2; j++)
                #pragma unroll
                for (int e = 0; e < 4; e++) s[j][e] = 0.f;

            #pragma unroll
            for (int c = 0; c < 8; c++) {
                #pragma unroll
                for (int j = 0; j < 2; j++) {
                    uint32_t b[2];
                    const float* kr = Ks + (n0 + j*8 + gid)*68 + c*8;
                    b[0] = __float_as_uint(kr[tg]);
                    b[1] = __float_as_uint(kr[tg + 4]);
                    mma1688_tf32(s[j], aq[c], b);
                }
            }

            float cm0 = fmaxf(fmaxf(s[0][0], s[0][1]), fmaxf(s[1][0], s[1][1]));
            float cm1 = fmaxf(fmaxf(s[0][2], s[0][3]), fmaxf(s[1][2], s[1][3]));
            cm0 = fmaxf(cm0, __shfl_xor_sync(~0u, cm0, 1));
            cm0 = fmaxf(cm0, __shfl_xor_sync(~0u, cm0, 2));
            cm1 = fmaxf(cm1, __shfl_xor_sync(~0u, cm1, 1));
            cm1 = fmaxf(cm1, __shfl_xor_sync(~0u, cm1, 2));
            float mn0 = fmaxf(mx0, cm0), mn1 = fmaxf(mx1, cm1);
            float sc0 = __expf(mx0 - mn0), sc1 = __expf(mx1 - mn1);
            mx0 = mn0; mx1 = mn1;
            #pragma unroll
            for (int j = 0; j < 2; j++) {
                s[j][0] = __expf(s[j][0] - mn0);
                s[j][1] = __expf(s[j][1] - mn0);
                s[j][2] = __expf(s[j][2] - mn1);
                s[j][3] = __expf(s[j][3] - mn1);
            }
            float rs0 = s[0][0] + s[0][1] + s[1][0] + s[1][1];
            float rs1 = s[0][2] + s[0][3] + s[1][2] + s[1][3];
            rs0 += __shfl_xor_sync(~0u, rs0, 1);
            rs0 += __shfl_xor_sync(~0u, rs0, 2);
            rs1 += __shfl_xor_sync(~0u, rs1, 1);
            rs1 += __shfl_xor_sync(~0u, rs1, 2);
            l0 = l0*sc0 + rs0;
            l1 = l1*sc1 + rs1;
            #pragma unroll
            for (int j = 0; j < 8; j++) {
                o_[j][0] *= sc0; o_[j][1] *= sc0;
                o_[j][2] *= sc1; o_[j][3] *= sc1;
            }

            #pragma unroll
            for (int j = 0; j < 2; j++) {
                Pw[gid*20     + j*8 + 2*tg]     = __uint_as_float(f2tfr(s[j][0]));
                Pw[gid*20     + j*8 + 2*tg + 1] = __uint_as_float(f2tfr(s[j][1]));
                Pw[(gid+8)*20 + j*8 + 2*tg]     = __uint_as_float(f2tfr(s[j][2]));
                Pw[(gid+8)*20 + j*8 + 2*tg + 1] = __uint_as_float(f2tfr(s[j][3]));
            }
            __syncwarp();
            #pragma unroll
            for (int kk = 0; kk < 2; kk++) {
                uint32_t ap[4];
                ap[0] = __float_as_uint(Pw[gid*20     + kk*8 + tg]);
                ap[1] = __float_as_uint(Pw[(gid+8)*20 + kk*8 + tg]);
                ap[2] = __float_as_uint(Pw[gid*20     + kk*8 + tg + 4]);
                ap[3] = __float_as_uint(Pw[(gid+8)*20 + kk*8 + tg + 4]);
                #pragma unroll
                for (int j = 0; j < 8; j++) {
                    uint32_t bv[2];
                    const float* vr = Vt + (j*8 + gid)*VLD + n0 + kk*8;
                    bv[0] = __float_as_uint(vr[tg]);
                    bv[1] = __float_as_uint(vr[tg + 4]);
                    mma1688_tf32(o_[j], ap, bv);
                }
            }
            __syncwarp();
        }

        float inv0 = 1.f / l0, inv1 = 1.f / l1;
        float* or0 = o + (base + m0 + gid)*384 + h*64;
        float* or1 = or0 + 8*384;
        #pragma unroll
        for (int j = 0; j < 8; j++) {
            *(float2*)(or0 + j*8 + 2*tg) = make_float2(o_[j][0]*inv0, o_[j][1]*inv0);
            *(float2*)(or1 + j*8 + 2*tg) = make_float2(o_[j][2]*inv1, o_[j][3]*inv1);
        }
    }
}

#define ATTN_SMEM(N) ((N*68 + 64*(N+4) + 8*16*20)*4)

// ---------------------------------------------------------------------------
// Merged multi-scale conv (one launch; block ranges dispatch the 3 scales)
// ---------------------------------------------------------------------------
template<int KS, int OHW, int POS>
__device__ __forceinline__ void conv_body(
    const float* __restrict__ x, const float* __restrict__ w,
    float* __restrict__ out, int blk)
{
    extern __shared__ float sp[];
    constexpr int PSZ = CHN*KS*KS;
    constexpr int NPB = (OHW*OHW + POS - 1) / POS;
    const int b = blk / NPB;
    const int pos0 = (blk % NPB) * POS;

    #pragma unroll
    for (int q = 0; q < POS; q++) {
        int pos = pos0 + q;
        if (pos >= OHW*OHW) break;
        int oy = pos / OHW, ox = pos % OHW;
        const float* xb = x + ((size_t)(b*CHN))*HX*HX + (size_t)oy*KS*HX + ox*KS;
        for (int p = threadIdx.x; p < PSZ; p += 256) {
            int ci = p / (KS*KS); int pp = p % (KS*KS);
            int ky = pp / KS, kx = pp % KS;
            sp[q*PSZ + p] = xb[((size_t)ci*HX + ky)*HX + kx];
        }
    }
    __syncthreads();

    const int co = threadIdx.x >> 4, ln = threadIdx.x & 15;
    const float* wp = w + (size_t)co * PSZ;
    float acc[POS];
    #pragma unroll
    for (int q = 0; q < POS; q++) acc[q] = 0.f;

    for (int p = ln; p < PSZ; p += 16) {
        float wv = wp[p];
        #pragma unroll
        for (int q = 0; q < POS; q++)
            acc[q] = fmaf(sp[q*PSZ + p], wv, acc[q]);
    }

    #pragma unroll
    for (int q = 0; q < POS; q++) {
        float a = acc[q];
        #pragma unroll
        for (int off = 8; off; off >>= 1)
            a += __shfl_xor_sync(0xffffffffu, a, off, 16);
        int pos = pos0 + q;
        if (ln == 0 && pos < OHW*OHW)
            out[(size_t)(b*CHN+co)*OHW*OHW + pos] = a;
    }
}

__global__ void __launch_bounds__(256) conv_all_kernel(
    const float* __restrict__ x, const float* __restrict__ cs18,
    const float* __restrict__ cs16, const float* __restrict__ cs14)
{
    int blk = blockIdx.x;
    if (blk < 16*28)           conv_body<18,14,7>(x, cs18, g_conv18, blk);
    else if (blk < 16*28+16*32) conv_body<16,16,8>(x, cs16, g_conv16, blk - 16*28);
    else                        conv_body<14,18,9>(x, cs14, g_conv14, blk - 16*28 - 16*32);
}
#define CONV_ALL_SMEM (7*CHN*18*18*4)
#define CONV_ALL_GRID (16*28 + 16*32 + 16*36)

// ---------------------------------------------------------------------------
// Merged pool + gram + per-batch argsort (one block per batch)
// ---------------------------------------------------------------------------
__global__ void __launch_bounds__(256) pool_gram_sort_kernel(
    const float* __restrict__ W, float* __restrict__ out_vals, float* __restrict__ out_idx)
{
    __shared__ float tok[77*16];
    __shared__ float ms[77*16];
    __shared__ float cm[256];
    __shared__ float nrm[16];
    __shared__ float wv[16];
    int b = blockIdx.x, tid = threadIdx.x;

    for (int i = tid; i < 77*16; i += 256) {
        int c = i & 15, l = i >> 4;
        float av = 0.f, mx = -1e30f;
        if (l < 16) {
            int li = l, py = li/4, px = li%4;
            const float* cb = g_conv18 + (size_t)(b*16+c)*14*14;
            for (int ky=0; ky<3; ky++) for (int kx=0; kx<3; kx++) {
                float v = cb[(py*3+ky)*14 + (px*3+kx)];
                av += v; mx = fmaxf(mx, v);
            }
        } else if (l < 41) {
            int li = l-16, py = li/5, px = li%5;
            const float* cb = g_conv16 + (size_t)(b*16+c)*16*16;
            for (int ky=0; ky<3; ky++) for (int kx=0; kx<3; kx++) {
                float v = cb[(py*3+ky)*16 + (px*3+kx)];
                av += v; mx = fmaxf(mx, v);
            }
        } else {
            int li = l-41, py = li/6, px = li%6;
            const float* cb = g_conv14 + (size_t)(b*16+c)*18*18;
            for (int ky=0; ky<3; ky++) for (int kx=0; kx<3; kx++) {
                float v = cb[(py*3+ky)*18 + (px*3+kx)];
                av += v; mx = fmaxf(mx, v);
            }
        }
        tok[i] = av*(1.f/9.f) + mx;
    }
    __syncthreads();

    for (int i = tid; i < 77*16; i += 256) {
        int l = i >> 4, d = i & 15;
        float s = 0.f;
        #pragma unroll
        for (int c = 0; c < 16; c++) s += tok[l*16+c] * W[c*16+d];
        ms[i] = s;
    }
    __syncthreads();
    {
        int c = tid >> 4, d = tid & 15;
        float s = 0.f;
        for (int l = 0; l < 77; l++) s += ms[l*16+c] * ms[l*16+d];
        cm[tid] = (c == d) ? 0.f : s;
    }
    __syncthreads();
    if (tid < 16) {
        float s = 0.f;
        #pragma unroll
        for (int d = 0; d < 16; d++) { float v = cm[tid*16+d]; s += v*v; }
        nrm[tid] = fmaxf(sqrtf(s), 1e-12f);
    }
    __syncthreads();
    float v = cm[tid] / nrm[tid >> 4];
    __syncthreads();
    cm[tid] = v;
    __syncthreads();
    if (tid < 16) {
        float s = 0.f;
        #pragma unroll
        for (int d = 0; d < 16; d++) s += fabsf(cm[tid*16+d]);
        g_wbuf[b*16 + tid] = s;
        wv[tid] = s;
    }
    __syncthreads();

    if (tid == 0) {
        float vv[16]; int id[16];
        for (int i = 0; i < 16; i++) { vv[i] = wv[i]; id[i] = i; }
        for (int i = 1; i < 16; i++) {
            float kv = vv[i]; int ki = id[i]; int j = i-1;
            while (j >= 0 && vv[j] < kv) { vv[j+1]=vv[j]; id[j+1]=id[j]; j--; }
            vv[j+1]=kv; id[j+1]=ki;
        }
        for (int i = 0; i < 16; i++) {
            g_order[b*16+i] = id[i];
            out_vals[b*16+i] = vv[i];
            out_idx[b*16+i]  = (float)id[i];
        }
    }
}

// ---------------------------------------------------------------------------
// Merged prep: im2col(z) + im2col(x) + patchw transpose
// ---------------------------------------------------------------------------
#define ZCOLT (NGRP*BB*NTZ*768)
#define XCOLT (NGRP*BB*NTX*768)
#define PWT   (384*768)
#define PREP_TOTAL (ZCOLT + XCOLT + PWT)

__device__ __forceinline__ void im2col_one(
    const float* __restrict__ img, float* __restrict__ A,
    int idx, int NT, int PW, int HW, int rowOff)
{
    int k = idx % 768; int m = idx / 768;
    int n = m % NT; int gb = m / NT;
    int b = gb & 15; int g = gb >> 4;
    int c = k >> 8; int rr = k & 255;
    int ky = rr >> 4, kx = rr & 15;
    int ch = g_order[b*16 + 3*g + c];
    int py = n / PW, px = n % PW;
    float mean, inv;
    if (c == 0)      { mean = 0.485f; inv = 1.f/0.229f; }
    else if (c == 1) { mean = 0.456f; inv = 1.f/0.224f; }
    else             { mean = 0.406f; inv = 1.f/0.225f; }
    float v = img[((size_t)(b*CHN+ch)*HW + py*16+ky)*HW + px*16+kx];
    size_t row = (size_t)gb*NTOT + rowOff + n;
    A[row*768 + k] = (v - mean) * inv;
}

__global__ void prep_kernel(const float* __restrict__ z, const float* __restrict__ x,
                            const float* __restrict__ patchw, float* __restrict__ col)
{
    int idx = blockIdx.x*256 + threadIdx.x;
    if (idx < ZCOLT) {
        im2col_one(z, col, idx, NTZ, 8, HZ, 0);
    } else if (idx < ZCOLT + XCOLT) {
        im2col_one(x, col, idx - ZCOLT, NTX, 16, HX, NTZ);
    } else if (idx < PREP_TOTAL) {
        int i = idx - ZCOLT - XCOLT;
        int nrow = i / 768, k = i % 768;
        g_patchw_t[k*384 + nrow] = patchw[i];
    }
}

// ---------------------------------------------------------------------------
// flat + channel-scaled copies (float4 vectorized)
// ---------------------------------------------------------------------------
__global__ void copy_cg_kernel(const float* __restrict__ img,
                               float* __restrict__ oflat, float* __restrict__ ocg,
                               int HW4, int total4)
{
    int i4 = blockIdx.x*256 + threadIdx.x;
    if (i4 >= total4) return;
    int bc = i4 / HW4;
    float w = g_wbuf[bc];
    float4 v = ((const float4*)img)[i4];
    ((float4*)oflat)[i4] = v;
    ((float4*)ocg)[i4] = make_float4(v.x*w, v.y*w, v.z*w, v.w*w);
}

// ---------------------------------------------------------------------------
// LayerNorm over E=384
// ---------------------------------------------------------------------------
__global__ void __launch_bounds__(128) ln_kernel(
    const float* __restrict__ in, float* __restrict__ out,
    const float* __restrict__ s, const float* __restrict__ bb)
{
    int row = blockIdx.x, tid = threadIdx.x;
    const float* ip = in + (size_t)row*384;
    float v0 = ip[tid], v1 = ip[tid+128], v2 = ip[tid+256];
    __shared__ float red[4];
    float loc = v0 + v1 + v2;
    #pragma unroll
    for (int o = 16; o; o >>= 1) loc += __shfl_xor_sync(~0u, loc, o);
    int w = tid >> 5, ln = tid & 31;
    if (ln == 0) red[w] = loc;
    __syncthreads();
    float mu = (red[0]+red[1]+red[2]+red[3]) * (1.f/384.f);
    float d0 = v0-mu, d1 = v1-mu, d2 = v2-mu;
    float loc2 = d0*d0 + d1*d1 + d2*d2;
    #pragma unroll
    for (int o = 16; o; o >>= 1) loc2 += __shfl_xor_sync(~0u, loc2, o);
    __syncthreads();
    if (ln == 0) red[w] = loc2;
    __syncthreads();
    float var = (red[0]+red[1]+red[2]+red[3]) * (1.f/384.f);
    float rs = rsqrtf(var + 1e-6f);
    float* op = out + (size_t)row*384;
    op[tid]     = d0*rs*s[tid]     + bb[tid];
    op[tid+128] = d1*rs*s[tid+128] + bb[tid+128];
    op[tid+256] = d2*rs*s[tid+256] + bb[tid+256];
}

// ---------------------------------------------------------------------------
// group-sum + final LayerNorm
// ---------------------------------------------------------------------------
__global__ void __launch_bounds__(128) final_kernel(
    const float* __restrict__ s, const float* __restrict__ bb, float* __restrict__ out)
{
    int row = blockIdx.x;
    int b = row / NTOT, n = row % NTOT;
    int tid = threadIdx.x;
    float v[3];
    #pragma unroll
    for (int i = 0; i < 3; i++) {
        int e = tid + 128*i;
        float a = 0.f;
        #pragma unroll
        for (int g = 0; g < 5; g++)
            a += g_t[(((size_t)(g*16+b)*NTOT + n)*384) + e];
        v[i] = a;
    }
    __shared__ float red[4];
    float loc = v[0]+v[1]+v[2];
    #pragma unroll
    for (int o = 16; o; o >>= 1) loc += __shfl_xor_sync(~0u, loc, o);
    int w = tid >> 5, ln = tid & 31;
    if (ln == 0) red[w] = loc;
    __syncthreads();
    float mu = (red[0]+red[1]+red[2]+red[3]) * (1.f/384.f);
    float d0 = v[0]-mu, d1 = v[1]-mu, d2 = v[2]-mu;
    float loc2 = d0*d0 + d1*d1 + d2*d2;
    #pragma unroll
    for (int o = 16; o; o >>= 1) loc2 += __shfl_xor_sync(~0u, loc2, o);
    __syncthreads();
    if (ln == 0) red[w] = loc2;
    __syncthreads();
    float var = (red[0]+red[1]+red[2]+red[3]) * (1.f/384.f);
    float rs = rsqrtf(var + 1e-6f);
    float* op = out + (size_t)row*384;
    op[tid]     = d0*rs*s[tid]     + bb[tid];
    op[tid+128] = d1*rs*s[tid+128] + bb[tid+128];
    op[tid+256] = d2*rs*s[tid+256] + bb[tid+256];
}

// ---------------------------------------------------------------------------
// Host side
// ---------------------------------------------------------------------------
static void run_gemm(const float* A, const float* B, const float* aux, float* C,
                     int M, int N, int K, int epi,
                     const float* pz = nullptr, const float* px = nullptr)
{
    dim3 grid(N/64, M/128);
    switch (epi) {
        case 0: gemm_tf32_kernel<0><<<grid,256,GEMM_SMEM_BYTES>>>(A,B,nullptr,C,M,N,K,nullptr,nullptr); break;
        case 1: gemm_tf32_kernel<1><<<grid,256,GEMM_SMEM_BYTES>>>(A,B,aux,C,M,N,K,nullptr,nullptr); break;
        case 2: gemm_tf32_kernel<2><<<grid,256,GEMM_SMEM_BYTES>>>(A,B,nullptr,C,M,N,K,nullptr,nullptr); break;
        case 4: gemm_tf32_kernel<4><<<grid,256,GEMM_SMEM_BYTES>>>(A,B,aux,C,M,N,K,pz,px); break;
        default: gemm_tf32_kernel<3><<<grid,256,GEMM_SMEM_BYTES>>>(A,B,aux,C,M,N,K,nullptr,nullptr); break;
    }
}

static void run_block(float* tptr, int i, int early, int fusePos,
    const float* ln1s, const float* ln1b, const float* qkvw, const float* projw,
    const float* ln2s, const float* ln2b, const float* mlp1w, const float* mlp2w,
    float* hbuf, float* qkvbuf, float* obuf, float* hidbuf,
    const float* posz, const float* posx)
{
    ln_kernel<<<MTOT,128>>>(tptr, hbuf, ln1s + i*384, ln1b + i*384);
    run_gemm(hbuf, qkvw + (size_t)i*384*1152, nullptr, qkvbuf, MTOT, 1152, 384, 0);
    if (early) {
        attn_mma_kernel<64> <<<GBN*NHD,256,ATTN_SMEM(64)>>>(qkvbuf, obuf, 0);
        attn_mma_kernel<256><<<GBN*NHD,256,ATTN_SMEM(256)>>>(qkvbuf, obuf, NTZ);
    } else {
        attn_mma_kernel<320><<<GBN*NHD,256,ATTN_SMEM(320)>>>(qkvbuf, obuf, 0);
    }
    run_gemm(obuf, projw + (size_t)i*384*384, tptr, tptr, MTOT, 384, 384, 3);
    ln_kernel<<<MTOT,128>>>(tptr, hbuf, ln2s + i*384, ln2b + i*384);
    run_gemm(hbuf, mlp1w + (size_t)i*384*1536, nullptr, hidbuf, MTOT, 1536, 384, 2);
    if (fusePos)
        run_gemm(hidbuf, mlp2w + (size_t)i*1536*384, tptr, tptr, MTOT, 384, 1536, 4, posz, posx);
    else
        run_gemm(hidbuf, mlp2w + (size_t)i*1536*384, tptr, tptr, MTOT, 384, 1536, 3);
}

extern "C" void kernel_launch(void* const* d_in, const int* in_sizes, int n_in,
                              void* d_out, int out_size)
{
    const float* z      = (const float*)d_in[0];
    const float* x      = (const float*)d_in[1];
    const float* cs18   = (const float*)d_in[2];
    const float* cs16   = (const float*)d_in[3];
    const float* cs14   = (const float*)d_in[4];
    const float* csMP   = (const float*)d_in[5];
    const float* patchw = (const float*)d_in[6];
    const float* patchb = (const float*)d_in[7];
    const float* posz   = (const float*)d_in[8];
    const float* posx   = (const float*)d_in[9];
    const float* ln1s   = (const float*)d_in[10];
    const float* ln1b   = (const float*)d_in[11];
    const float* qkvw   = (const float*)d_in[12];
    const float* projw  = (const float*)d_in[13];
    const float* ln2s   = (const float*)d_in[14];
    const float* ln2b   = (const float*)d_in[15];
    const float* mlp1w  = (const float*)d_in[16];
    const float* mlp2w  = (const float*)d_in[17];
    const float* norms  = (const float*)d_in[18];
    const float* normb  = (const float*)d_in[19];
    float* out = (float*)d_out;

    float *p_t, *p_qkv, *p_h, *p_o, *p_hid, *p_col, *p_patchw_t;
    cudaGetSymbolAddress((void**)&p_t, g_t);
    cudaGetSymbolAddress((void**)&p_qkv, g_qkv);
    cudaGetSymbolAddress((void**)&p_h, g_h);
    cudaGetSymbolAddress((void**)&p_o, g_o);
    cudaGetSymbolAddress((void**)&p_hid, g_hidden);
    cudaGetSymbolAddress((void**)&p_col, g_col);
    cudaGetSymbolAddress((void**)&p_patchw_t, g_patchw_t);

    cudaFuncSetAttribute(attn_mma_kernel<64>,  cudaFuncAttributeMaxDynamicSharedMemorySize, ATTN_SMEM(64));
    cudaFuncSetAttribute(attn_mma_kernel<256>, cudaFuncAttributeMaxDynamicSharedMemorySize, ATTN_SMEM(256));
    cudaFuncSetAttribute(attn_mma_kernel<320>, cudaFuncAttributeMaxDynamicSharedMemorySize, ATTN_SMEM(320));
    cudaFuncSetAttribute(gemm_tf32_kernel<0>, cudaFuncAttributeMaxDynamicSharedMemorySize, GEMM_SMEM_BYTES);
    cudaFuncSetAttribute(gemm_tf32_kernel<1>, cudaFuncAttributeMaxDynamicSharedMemorySize, GEMM_SMEM_BYTES);
    cudaFuncSetAttribute(gemm_tf32_kernel<2>, cudaFuncAttributeMaxDynamicSharedMemorySize, GEMM_SMEM_BYTES);
    cudaFuncSetAttribute(gemm_tf32_kernel<3>, cudaFuncAttributeMaxDynamicSharedMemorySize, GEMM_SMEM_BYTES);
    cudaFuncSetAttribute(gemm_tf32_kernel<4>, cudaFuncAttributeMaxDynamicSharedMemorySize, GEMM_SMEM_BYTES);
    cudaFuncSetAttribute(conv_all_kernel, cudaFuncAttributeMaxDynamicSharedMemorySize, CONV_ALL_SMEM);

    // launch 1: merged multi-scale convs
    conv_all_kernel<<<CONV_ALL_GRID,256,CONV_ALL_SMEM>>>(x, cs18, cs16, cs14);
    // launch 2: pool + gram + per-batch argsort
    pool_gram_sort_kernel<<<16,256>>>(csMP, out + OFF_OV, out + OFF_OI);
    // launch 3: im2col z + im2col x + patch weight transpose
    prep_kernel<<<PREP_TOTAL/256,256>>>(z, x, patchw, p_col);
    // launch 4: patch-embed GEMM (profiled slot)
    run_gemm(p_col, p_patchw_t, patchb, p_t, MTOT, 384, 768, 1);

    // flat + channel-scaled copies
    copy_cg_kernel<<<(1048576 + 255)/256, 256>>>(z, out + OFF_ZF, out + OFF_ZCG, HZ*HZ/4, 1048576);
    copy_cg_kernel<<<(4194304 + 255)/256, 256>>>(x, out + OFF_XF, out + OFF_XCG, HX*HX/4, 4194304);

    // early transformer blocks (segment-local attention); block 1 fuses +pos
    run_block(p_t, 0, 1, 0, ln1s, ln1b, qkvw, projw, ln2s, ln2b,
              mlp1w, mlp2w, p_h, p_qkv, p_o, p_hid, posz, posx);
    run_block(p_t, 1, 1, 1, ln1s, ln1b, qkvw, projw, ln2s, ln2b,
              mlp1w, mlp2w, p_h, p_qkv, p_o, p_hid, posz, posx);

    // late blocks (full attention)
    for (int i = 2; i < 4; i++)
        run_block(p_t, i, 0, 0, ln1s, ln1b, qkvw, projw, ln2s, ln2b,
                  mlp1w, mlp2w, p_h, p_qkv, p_o, p_hid, posz, posx);

    // group-sum + final LayerNorm
    final_kernel<<<16*NTOT, 128>>>(norms, normb, out + OFF_OUT);
}

// round 15
// speedup vs baseline: 1.0661x; 1.0661x over previous
#include <cuda_runtime.h>
#include <cuda_bf16.h>
#include <math.h>
#include <stdint.h>

// ---------------------------------------------------------------------------
// Problem constants
// ---------------------------------------------------------------------------
#define BB    16
#define CHN   16
#define HZ    128
#define HX    256
#define EMB   384
#define NHD   6
#define NGRP  5
#define NTZ   64
#define NTX   256
#define GBN   80
#define NTOT  320
#define MTOT  25600    // GBN * NTOT

#define OFF_OUT  0
#define OFF_ZF   1966080
#define OFF_XF   6160384
#define OFF_ZCG  22937600
#define OFF_XCG  27131904
#define OFF_OV   43909120
#define OFF_OI   43909376

// ---------------------------------------------------------------------------
// Device scratch
// ---------------------------------------------------------------------------
__device__ float g_conv18[16*16*14*14];
__device__ float g_conv16[16*16*16*16];
__device__ float g_conv14[16*16*18*18];
__device__ float g_wbuf[256];
__device__ int   g_order[256];
__device__ float g_t[25600*384];        // unified token buffer (concat layout)
__device__ float g_h[25600*384];
__device__ float g_qkv[25600*1152];
__device__ float g_o[25600*384];
__device__ float g_hidden[25600*1536];
__device__ float g_col[25600*768];
__device__ float g_patchw_t[768*384];

// ---------------------------------------------------------------------------
// PTX helpers
// ---------------------------------------------------------------------------
__device__ __forceinline__ void mma1688_tf32(float* d, const uint32_t* a, const uint32_t* b) {
    asm volatile("mma.sync.aligned.m16n8k8.row.col.f32.tf32.tf32.f32 "
        "{%0,%1,%2,%3},{%4,%5,%6,%7},{%8,%9},{%0,%1,%2,%3};"
        : "+f"(d[0]),"+f"(d[1]),"+f"(d[2]),"+f"(d[3])
        : "r"(a[0]),"r"(a[1]),"r"(a[2]),"r"(a[3]), "r"(b[0]),"r"(b[1]));
}
__device__ __forceinline__ void cp16(void* dst_smem, const void* src) {
    uint32_t d = (uint32_t)__cvta_generic_to_shared(dst_smem);
    asm volatile("cp.async.cg.shared.global [%0],[%1],16;" :: "r"(d), "l"(src));
}
__device__ __forceinline__ void ldsm4(uint32_t* d, uint32_t a) {
    asm volatile("ldmatrix.sync.aligned.m8n8.x4.shared.b16 {%0,%1,%2,%3},[%4];"
        : "=r"(d[0]),"=r"(d[1]),"=r"(d[2]),"=r"(d[3]) : "r"(a));
}
__device__ __forceinline__ uint32_t f2tfr(float f) {
    uint32_t u;
    asm("cvt.rna.tf32.f32 %0, %1;" : "=r"(u) : "f"(f));
    return u;
}
__device__ __forceinline__ float tf32r(float f) {
    return __uint_as_float(f2tfr(f));
}

__device__ __forceinline__ float gelu_f(float x)
{
    float x3 = x*x*x;
    return 0.5f*x*(1.0f + tanhf(0.7978845608028654f*(x + 0.044715f*x3)));
}

// ---------------------------------------------------------------------------
// TF32 tensor-core GEMM — exact R13 configuration (best known):
// 128x128x32 block tile, 8 warps (2Mx4N), warp tile 64x32, 3-stage cp.async,
// ldmatrix A-fragments, 2 CTAs/SM.
// EPI: 0 none, 1 +bias, 2 gelu, 3 +residual, 4 +residual +pos
// ---------------------------------------------------------------------------
#define AS_W   36
#define BS_W   136
#define AS_TILE (128*AS_W)
#define BS_TILE (32*BS_W)
#define GEMM_SMEM_BYTES ((3*AS_TILE + 3*BS_TILE)*4)

template<int EPI>
__global__ void __launch_bounds__(256,2) gemm_tf32_kernel(
    const float* __restrict__ A, const float* __restrict__ B,
    const float* __restrict__ aux, float* __restrict__ C,
    int M, int N, int K,
    const float* __restrict__ pz, const float* __restrict__ px)
{
    extern __shared__ uint32_t sm_[];
    uint32_t* AsBase = sm_;
    uint32_t* BsBase = sm_ + 3*AS_TILE;

    const int tid  = threadIdx.x;
    const int warp = tid >> 5, lane = tid & 31;
    const int wm = (warp & 1) * 64;
    const int wn = (warp >> 1) * 32;
    const int mBase = blockIdx.y * 128, nBase = blockIdx.x * 128;
    const int gid = lane >> 2, tg = lane & 3;
    const int KT = K >> 5;

    int arow[4], acof[4], bkr[4], bnc[4];
    #pragma unroll
    for (int c = 0; c < 4; c++) {
        int ch = tid + c*256;
        arow[c] = ch >> 3;  acof[c] = (ch & 7) * 4;
        bkr[c]  = ch >> 5;  bnc[c]  = (ch & 31) * 4;
    }

    const int lmRow = wm + (lane & 15);
    const int lmCol = (lane >> 4) * 4;
    uint32_t aAddrStage[3];
    #pragma unroll
    for (int st = 0; st < 3; st++)
        aAddrStage[st] = (uint32_t)__cvta_generic_to_shared(
            AsBase + st*AS_TILE + lmRow*AS_W + lmCol);

    float acc[4][4][4];
    #pragma unroll
    for (int i = 0; i < 4; i++)
        #pragma unroll
        for (int j = 0; j < 4; j++)
            #pragma unroll
            for (int e = 0; e < 4; e++) acc[i][j][e] = 0.f;

    auto issue = [&](int kt, int buf) {
        int k0 = kt * 32;
        uint32_t* as = AsBase + buf*AS_TILE;
        uint32_t* bs = BsBase + buf*BS_TILE;
        #pragma unroll
        for (int c = 0; c < 4; c++) {
            cp16(as + arow[c]*AS_W + acof[c],
                 A + (size_t)(mBase + arow[c])*K + k0 + acof[c]);
            cp16(bs + bkr[c]*BS_W + bnc[c],
                 B + (size_t)(k0 + bkr[c])*N + nBase + bnc[c]);
        }
        asm volatile("cp.async.commit_group;");
    };

    issue(0, 0);
    issue(1, 1);

    for (int kt = 0; kt < KT; kt++) {
        if (kt + 1 < KT) asm volatile("cp.async.wait_group 1;");
        else             asm volatile("cp.async.wait_group 0;");
        __syncthreads();
        if (kt + 2 < KT) issue(kt + 2, (kt + 2) % 3);

        const int stg = kt % 3;
        const uint32_t aAddr = aAddrStage[stg];
        const uint32_t* bs = BsBase + stg*BS_TILE;
        #pragma unroll
        for (int ks = 0; ks < 32; ks += 8) {
            uint32_t a[4][4], b[4][2];
            #pragma unroll
            for (int mt = 0; mt < 4; mt++)
                ldsm4(a[mt], aAddr + (mt*16*AS_W + ks)*4);
            #pragma unroll
            for (int nt = 0; nt < 4; nt++) {
                b[nt][0] = bs[(ks + tg    )*BS_W + wn + nt*8 + gid];
                b[nt][1] = bs[(ks + tg + 4)*BS_W + wn + nt*8 + gid];
            }
            #pragma unroll
            for (int mt = 0; mt < 4; mt++)
                #pragma unroll
                for (int nt = 0; nt < 4; nt++)
                    mma1688_tf32(acc[mt][nt], a[mt], b[nt]);
        }
    }

    #pragma unroll
    for (int mt = 0; mt < 4; mt++) {
        #pragma unroll
        for (int nt = 0; nt < 4; nt++) {
            #pragma unroll
            for (int half = 0; half < 2; half++) {
                int m = mBase + wm + mt*16 + gid + half*8;
                int n = nBase + wn + nt*8 + tg*2;
                float v0 = acc[mt][nt][half*2];
                float v1 = acc[mt][nt][half*2+1];
                if (EPI == 1) { v0 += aux[n]; v1 += aux[n+1]; }
                else if (EPI == 2) { v0 = gelu_f(v0); v1 = gelu_f(v1); }
                else if (EPI == 3) {
                    const float2 rr = *(const float2*)(aux + (size_t)m*N + n);
                    v0 += rr.x; v1 += rr.y;
                } else if (EPI == 4) {
                    const float2 rr = *(const float2*)(aux + (size_t)m*N + n);
                    v0 += rr.x; v1 += rr.y;
                    int ntok = m % NTOT;
                    const float* pp = (ntok < NTZ)
                        ? (pz + (size_t)ntok*384 + n)
                        : (px + (size_t)(ntok-NTZ)*384 + n);
                    v0 += pp[0]; v1 += pp[1];
                }
                *(float2*)(C + (size_t)m*N + n) = make_float2(v0, v1);
            }
        }
    }
}

// ---------------------------------------------------------------------------
// Tensor-core flash attention (tf32 mma, online softmax) — unchanged
// ---------------------------------------------------------------------------
template<int N>
__global__ void __launch_bounds__(256) attn_mma_kernel(
    const float* __restrict__ qkv, float* __restrict__ o, int rowOff)
{
    extern __shared__ float smf[];
    float* Ks = smf;                          // N*68
    float* Vt = smf + N*68;                   // 64*(N+4)
    float* Ps = smf + N*68 + 64*(N+4);        // 8 * 16*20

    const int gb = blockIdx.x / NHD, h = blockIdx.x % NHD;
    const int tid = threadIdx.x;
    const size_t base = (size_t)gb * NTOT + rowOff;
    const int VLD = N + 4;

    for (int idx = tid; idx < N*64; idx += 256) {
        int n = idx >> 6, d = idx & 63;
        const float* p = qkv + (base + n)*1152 + h*64 + d;
        Ks[n*68 + d]   = tf32r(p[384]);
        Vt[d*VLD + n]  = tf32r(p[768]);
    }
    __syncthreads();

    const int warp = tid >> 5, lane = tid & 31;
    const int gid = lane >> 2, tg = lane & 3;
    float* Pw = Ps + warp * (16*20);
    constexpr int NT = N / 16;

    for (int mt = warp; mt < NT; mt += 8) {
        int m0 = mt * 16;
        uint32_t aq[8][4];
        const float* q0 = qkv + (base + m0 + gid)*1152 + h*64;
        const float* q1 = q0 + 8*1152;
        #pragma unroll
        for (int c = 0; c < 8; c++) {
            aq[c][0] = f2tfr(q0[c*8 + tg]     * 0.125f);
            aq[c][1] = f2tfr(q1[c*8 + tg]     * 0.125f);
            aq[c][2] = f2tfr(q0[c*8 + tg + 4] * 0.125f);
            aq[c][3] = f2tfr(q1[c*8 + tg + 4] * 0.125f);
        }

        float o_[8][4];
        #pragma unroll
        for (int j = 0; j < 8; j++)
            #pragma unroll
            for (int e = 0; e < 4; e++) o_[j][e] = 0.f;
        float mx0 = -1e30f, mx1 = -1e30f, l0 = 0.f, l1 = 0.f;

        for (int n0 = 0; n0 < N; n0 += 16) {
            float s[2][4];
            #pragma unroll
            for (int j = 0; j < 2; j++)
                #pragma unroll
                for (int e = 0; e < 4; e++) s[j][e] = 0.f;

            #pragma unroll
            for (int c = 0; c < 8; c++) {
                #pragma unroll
                for (int j = 0; j < 2; j++) {
                    uint32_t b[2];
                    const float* kr = Ks + (n0 + j*8 + gid)*68 + c*8;
                    b[0] = __float_as_uint(kr[tg]);
                    b[1] = __float_as_uint(kr[tg + 4]);
                    mma1688_tf32(s[j], aq[c], b);
                }
            }

            float cm0 = fmaxf(fmaxf(s[0][0], s[0][1]), fmaxf(s[1][0], s[1][1]));
            float cm1 = fmaxf(fmaxf(s[0][2], s[0][3]), fmaxf(s[1][2], s[1][3]));
            cm0 = fmaxf(cm0, __shfl_xor_sync(~0u, cm0, 1));
            cm0 = fmaxf(cm0, __shfl_xor_sync(~0u, cm0, 2));
            cm1 = fmaxf(cm1, __shfl_xor_sync(~0u, cm1, 1));
            cm1 = fmaxf(cm1, __shfl_xor_sync(~0u, cm1, 2));
            float mn0 = fmaxf(mx0, cm0), mn1 = fmaxf(mx1, cm1);
            float sc0 = __expf(mx0 - mn0), sc1 = __expf(mx1 - mn1);
            mx0 = mn0; mx1 = mn1;
            #pragma unroll
            for (int j = 0; j < 2; j++) {
                s[j][0] = __expf(s[j][0] - mn0);
                s[j][1] = __expf(s[j][1] - mn0);
                s[j][2] = __expf(s[j][2] - mn1);
                s[j][3] = __expf(s[j][3] - mn1);
            }
            float rs0 = s[0][0] + s[0][1] + s[1][0] + s[1][1];
            float rs1 = s[0][2] + s[0][3] + s[1][2] + s[1][3];
            rs0 += __shfl_xor_sync(~0u, rs0, 1);
            rs0 += __shfl_xor_sync(~0u, rs0, 2);
            rs1 += __shfl_xor_sync(~0u, rs1, 1);
            rs1 += __shfl_xor_sync(~0u, rs1, 2);
            l0 = l0*sc0 + rs0;
            l1 = l1*sc1 + rs1;
            #pragma unroll
            for (int j = 0; j < 8; j++) {
                o_[j][0] *= sc0; o_[j][1] *= sc0;
                o_[j][2] *= sc1; o_[j][3] *= sc1;
            }

            #pragma unroll
            for (int j = 0; j < 2; j++) {
                Pw[gid*20     + j*8 + 2*tg]     = __uint_as_float(f2tfr(s[j][0]));
                Pw[gid*20     + j*8 + 2*tg + 1] = __uint_as_float(f2tfr(s[j][1]));
                Pw[(gid+8)*20 + j*8 + 2*tg]     = __uint_as_float(f2tfr(s[j][2]));
                Pw[(gid+8)*20 + j*8 + 2*tg + 1] = __uint_as_float(f2tfr(s[j][3]));
            }
            __syncwarp();
            #pragma unroll
            for (int kk = 0; kk < 2; kk++) {
                uint32_t ap[4];
                ap[0] = __float_as_uint(Pw[gid*20     + kk*8 + tg]);
                ap[1] = __float_as_uint(Pw[(gid+8)*20 + kk*8 + tg]);
                ap[2] = __float_as_uint(Pw[gid*20     + kk*8 + tg + 4]);
                ap[3] = __float_as_uint(Pw[(gid+8)*20 + kk*8 + tg + 4]);
                #pragma unroll
                for (int j = 0; j < 8; j++) {
                    uint32_t bv[2];
                    const float* vr = Vt + (j*8 + gid)*VLD + n0 + kk*8;
                    bv[0] = __float_as_uint(vr[tg]);
                    bv[1] = __float_as_uint(vr[tg + 4]);
                    mma1688_tf32(o_[j], ap, bv);
                }
            }
            __syncwarp();
        }

        float inv0 = 1.f / l0, inv1 = 1.f / l1;
        float* or0 = o + (base + m0 + gid)*384 + h*64;
        float* or1 = or0 + 8*384;
        #pragma unroll
        for (int j = 0; j < 8; j++) {
            *(float2*)(or0 + j*8 + 2*tg) = make_float2(o_[j][0]*inv0, o_[j][1]*inv0);
            *(float2*)(or1 + j*8 + 2*tg) = make_float2(o_[j][2]*inv1, o_[j][3]*inv1);
        }
    }
}

#define ATTN_SMEM(N) ((N*68 + 64*(N+4) + 8*16*20)*4)

// ---------------------------------------------------------------------------
// Merged multi-scale conv (one launch; block ranges dispatch the 3 scales)
// ---------------------------------------------------------------------------
template<int KS, int OHW, int POS>
__device__ __forceinline__ void conv_body(
    const float* __restrict__ x, const float* __restrict__ w,
    float* __restrict__ out, int blk)
{
    extern __shared__ float sp[];
    constexpr int PSZ = CHN*KS*KS;
    constexpr int NPB = (OHW*OHW + POS - 1) / POS;
    const int b = blk / NPB;
    const int pos0 = (blk % NPB) * POS;

    #pragma unroll
    for (int q = 0; q < POS; q++) {
        int pos = pos0 + q;
        if (pos >= OHW*OHW) break;
        int oy = pos / OHW, ox = pos % OHW;
        const float* xb = x + ((size_t)(b*CHN))*HX*HX + (size_t)oy*KS*HX + ox*KS;
        for (int p = threadIdx.x; p < PSZ; p += 256) {
            int ci = p / (KS*KS); int pp = p % (KS*KS);
            int ky = pp / KS, kx = pp % KS;
            sp[q*PSZ + p] = xb[((size_t)ci*HX + ky)*HX + kx];
        }
    }
    __syncthreads();

    const int co = threadIdx.x >> 4, ln = threadIdx.x & 15;
    const float* wp = w + (size_t)co * PSZ;
    float acc[POS];
    #pragma unroll
    for (int q = 0; q < POS; q++) acc[q] = 0.f;

    for (int p = ln; p < PSZ; p += 16) {
        float wv = wp[p];
        #pragma unroll
        for (int q = 0; q < POS; q++)
            acc[q] = fmaf(sp[q*PSZ + p], wv, acc[q]);
    }

    #pragma unroll
    for (int q = 0; q < POS; q++) {
        float a = acc[q];
        #pragma unroll
        for (int off = 8; off; off >>= 1)
            a += __shfl_xor_sync(0xffffffffu, a, off, 16);
        int pos = pos0 + q;
        if (ln == 0 && pos < OHW*OHW)
            out[(size_t)(b*CHN+co)*OHW*OHW + pos] = a;
    }
}

__global__ void __launch_bounds__(256) conv_all_kernel(
    const float* __restrict__ x, const float* __restrict__ cs18,
    const float* __restrict__ cs16, const float* __restrict__ cs14)
{
    int blk = blockIdx.x;
    if (blk < 16*28)           conv_body<18,14,7>(x, cs18, g_conv18, blk);
    else if (blk < 16*28+16*32) conv_body<16,16,8>(x, cs16, g_conv16, blk - 16*28);
    else                        conv_body<14,18,9>(x, cs14, g_conv14, blk - 16*28 - 16*32);
}
#define CONV_ALL_SMEM (7*CHN*18*18*4)
#define CONV_ALL_GRID (16*28 + 16*32 + 16*36)

// ---------------------------------------------------------------------------
// Merged pool + gram + per-batch argsort (one block per batch)
// ---------------------------------------------------------------------------
__global__ void __launch_bounds__(256) pool_gram_sort_kernel(
    const float* __restrict__ W, float* __restrict__ out_vals, float* __restrict__ out_idx)
{
    __shared__ float tok[77*16];
    __shared__ float ms[77*16];
    __shared__ float cm[256];
    __shared__ float nrm[16];
    __shared__ float wv[16];
    int b = blockIdx.x, tid = threadIdx.x;

    for (int i = tid; i < 77*16; i += 256) {
        int c = i & 15, l = i >> 4;
        float av = 0.f, mx = -1e30f;
        if (l < 16) {
            int li = l, py = li/4, px = li%4;
            const float* cb = g_conv18 + (size_t)(b*16+c)*14*14;
            for (int ky=0; ky<3; ky++) for (int kx=0; kx<3; kx++) {
                float v = cb[(py*3+ky)*14 + (px*3+kx)];
                av += v; mx = fmaxf(mx, v);
            }
        } else if (l < 41) {
            int li = l-16, py = li/5, px = li%5;
            const float* cb = g_conv16 + (size_t)(b*16+c)*16*16;
            for (int ky=0; ky<3; ky++) for (int kx=0; kx<3; kx++) {
                float v = cb[(py*3+ky)*16 + (px*3+kx)];
                av += v; mx = fmaxf(mx, v);
            }
        } else {
            int li = l-41, py = li/6, px = li%6;
            const float* cb = g_conv14 + (size_t)(b*16+c)*18*18;
            for (int ky=0; ky<3; ky++) for (int kx=0; kx<3; kx++) {
                float v = cb[(py*3+ky)*18 + (px*3+kx)];
                av += v; mx = fmaxf(mx, v);
            }
        }
        tok[i] = av*(1.f/9.f) + mx;
    }
    __syncthreads();

    for (int i = tid; i < 77*16; i += 256) {
        int l = i >> 4, d = i & 15;
        float s = 0.f;
        #pragma unroll
        for (int c = 0; c < 16; c++) s += tok[l*16+c] * W[c*16+d];
        ms[i] = s;
    }
    __syncthreads();
    {
        int c = tid >> 4, d = tid & 15;
        float s = 0.f;
        for (int l = 0; l < 77; l++) s += ms[l*16+c] * ms[l*16+d];
        cm[tid] = (c == d) ? 0.f : s;
    }
    __syncthreads();
    if (tid < 16) {
        float s = 0.f;
        #pragma unroll
        for (int d = 0; d < 16; d++) { float v = cm[tid*16+d]; s += v*v; }
        nrm[tid] = fmaxf(sqrtf(s), 1e-12f);
    }
    __syncthreads();
    float v = cm[tid] / nrm[tid >> 4];
    __syncthreads();
    cm[tid] = v;
    __syncthreads();
    if (tid < 16) {
        float s = 0.f;
        #pragma unroll
        for (int d = 0; d < 16; d++) s += fabsf(cm[tid*16+d]);
        g_wbuf[b*16 + tid] = s;
        wv[tid] = s;
    }
    __syncthreads();

    if (tid == 0) {
        float vv[16]; int id[16];
        for (int i = 0; i < 16; i++) { vv[i] = wv[i]; id[i] = i; }
        for (int i = 1; i < 16; i++) {
            float kv = vv[i]; int ki = id[i]; int j = i-1;
            while (j >= 0 && vv[j] < kv) { vv[j+1]=vv[j]; id[j+1]=id[j]; j--; }
            vv[j+1]=kv; id[j+1]=ki;
        }
        for (int i = 0; i < 16; i++) {
            g_order[b*16+i] = id[i];
            out_vals[b*16+i] = vv[i];
            out_idx[b*16+i]  = (float)id[i];
        }
    }
}

// ---------------------------------------------------------------------------
// Merged prep: im2col(z) + im2col(x) + patchw transpose
// ---------------------------------------------------------------------------
#define ZCOLT (NGRP*BB*NTZ*768)
#define XCOLT (NGRP*BB*NTX*768)
#define PWT   (384*768)
#define PREP_TOTAL (ZCOLT + XCOLT + PWT)

__device__ __forceinline__ void im2col_one(
    const float* __restrict__ img, float* __restrict__ A,
    int idx, int NT, int PW, int HW, int rowOff)
{
    int k = idx % 768; int m = idx / 768;
    int n = m % NT; int gb = m / NT;
    int b = gb & 15; int g = gb >> 4;
    int c = k >> 8; int rr = k & 255;
    int ky = rr >> 4, kx = rr & 15;
    int ch = g_order[b*16 + 3*g + c];
    int py = n / PW, px = n % PW;
    float mean, inv;
    if (c == 0)      { mean = 0.485f; inv = 1.f/0.229f; }
    else if (c == 1) { mean = 0.456f; inv = 1.f/0.224f; }
    else             { mean = 0.406f; inv = 1.f/0.225f; }
    float v = img[((size_t)(b*CHN+ch)*HW + py*16+ky)*HW + px*16+kx];
    size_t row = (size_t)gb*NTOT + rowOff + n;
    A[row*768 + k] = (v - mean) * inv;
}

__global__ void prep_kernel(const float* __restrict__ z, const float* __restrict__ x,
                            const float* __restrict__ patchw, float* __restrict__ col)
{
    int idx = blockIdx.x*256 + threadIdx.x;
    if (idx < ZCOLT) {
        im2col_one(z, col, idx, NTZ, 8, HZ, 0);
    } else if (idx < ZCOLT + XCOLT) {
        im2col_one(x, col, idx - ZCOLT, NTX, 16, HX, NTZ);
    } else if (idx < PREP_TOTAL) {
        int i = idx - ZCOLT - XCOLT;
        int nrow = i / 768, k = i % 768;
        g_patchw_t[k*384 + nrow] = patchw[i];
    }
}

// ---------------------------------------------------------------------------
// Merged flat + channel-scaled copies for z AND x (float4, range dispatch)
// ---------------------------------------------------------------------------
#define ZQ (BB*CHN*HZ*HZ/4)   // 1,048,576
#define XQ (BB*CHN*HX*HX/4)   // 4,194,304

__global__ void copy_all_kernel(const float* __restrict__ z, const float* __restrict__ x,
                                float* __restrict__ out)
{
    int i4 = blockIdx.x*256 + threadIdx.x;
    if (i4 < ZQ) {
        int bc = i4 / (HZ*HZ/4);
        float w = g_wbuf[bc];
        float4 v = ((const float4*)z)[i4];
        ((float4*)(out + OFF_ZF))[i4] = v;
        ((float4*)(out + OFF_ZCG))[i4] = make_float4(v.x*w, v.y*w, v.z*w, v.w*w);
    } else if (i4 < ZQ + XQ) {
        int j4 = i4 - ZQ;
        int bc = j4 / (HX*HX/4);
        float w = g_wbuf[bc];
        float4 v = ((const float4*)x)[j4];
        ((float4*)(out + OFF_XF))[j4] = v;
        ((float4*)(out + OFF_XCG))[j4] = make_float4(v.x*w, v.y*w, v.z*w, v.w*w);
    }
}

// ---------------------------------------------------------------------------
// LayerNorm over E=384
// ---------------------------------------------------------------------------
__global__ void __launch_bounds__(128) ln_kernel(
    const float* __restrict__ in, float* __restrict__ out,
    const float* __restrict__ s, const float* __restrict__ bb)
{
    int row = blockIdx.x, tid = threadIdx.x;
    const float* ip = in + (size_t)row*384;
    float v0 = ip[tid], v1 = ip[tid+128], v2 = ip[tid+256];
    __shared__ float red[4];
    float loc = v0 + v1 + v2;
    #pragma unroll
    for (int o = 16; o; o >>= 1) loc += __shfl_xor_sync(~0u, loc, o);
    int w = tid >> 5, ln = tid & 31;
    if (ln == 0) red[w] = loc;
    __syncthreads();
    float mu = (red[0]+red[1]+red[2]+red[3]) * (1.f/384.f);
    float d0 = v0-mu, d1 = v1-mu, d2 = v2-mu;
    float loc2 = d0*d0 + d1*d1 + d2*d2;
    #pragma unroll
    for (int o = 16; o; o >>= 1) loc2 += __shfl_xor_sync(~0u, loc2, o);
    __syncthreads();
    if (ln == 0) red[w] = loc2;
    __syncthreads();
    float var = (red[0]+red[1]+red[2]+red[3]) * (1.f/384.f);
    float rs = rsqrtf(var + 1e-6f);
    float* op = out + (size_t)row*384;
    op[tid]     = d0*rs*s[tid]     + bb[tid];
    op[tid+128] = d1*rs*s[tid+128] + bb[tid+128];
    op[tid+256] = d2*rs*s[tid+256] + bb[tid+256];
}

// ---------------------------------------------------------------------------
// group-sum + final LayerNorm
// ---------------------------------------------------------------------------
__global__ void __launch_bounds__(128) final_kernel(
    const float* __restrict__ s, const float* __restrict__ bb, float* __restrict__ out)
{
    int row = blockIdx.x;
    int b = row / NTOT, n = row % NTOT;
    int tid = threadIdx.x;
    float v[3];
    #pragma unroll
    for (int i = 0; i < 3; i++) {
        int e = tid + 128*i;
        float a = 0.f;
        #pragma unroll
        for (int g = 0; g < 5; g++)
            a += g_t[(((size_t)(g*16+b)*NTOT + n)*384) + e];
        v[i] = a;
    }
    __shared__ float red[4];
    float loc = v[0]+v[1]+v[2];
    #pragma unroll
    for (int o = 16; o; o >>= 1) loc += __shfl_xor_sync(~0u, loc, o);
    int w = tid >> 5, ln = tid & 31;
    if (ln == 0) red[w] = loc;
    __syncthreads();
    float mu = (red[0]+red[1]+red[2]+red[3]) * (1.f/384.f);
    float d0 = v[0]-mu, d1 = v[1]-mu, d2 = v[2]-mu;
    float loc2 = d0*d0 + d1*d1 + d2*d2;
    #pragma unroll
    for (int o = 16; o; o >>= 1) loc2 += __shfl_xor_sync(~0u, loc2, o);
    __syncthreads();
    if (ln == 0) red[w] = loc2;
    __syncthreads();
    float var = (red[0]+red[1]+red[2]+red[3]) * (1.f/384.f);
    float rs = rsqrtf(var + 1e-6f);
    float* op = out + (size_t)row*384;
    op[tid]     = d0*rs*s[tid]     + bb[tid];
    op[tid+128] = d1*rs*s[tid+128] + bb[tid+128];
    op[tid+256] = d2*rs*s[tid+256] + bb[tid+256];
}

// ---------------------------------------------------------------------------
// Host side
// ---------------------------------------------------------------------------
static void run_gemm(const float* A, const float* B, const float* aux, float* C,
                     int M, int N, int K, int epi,
                     const float* pz = nullptr, const float* px = nullptr)
{
    dim3 grid(N/128, M/128);
    switch (epi) {
        case 0: gemm_tf32_kernel<0><<<grid,256,GEMM_SMEM_BYTES>>>(A,B,nullptr,C,M,N,K,nullptr,nullptr); break;
        case 1: gemm_tf32_kernel<1><<<grid,256,GEMM_SMEM_BYTES>>>(A,B,aux,C,M,N,K,nullptr,nullptr); break;
        case 2: gemm_tf32_kernel<2><<<grid,256,GEMM_SMEM_BYTES>>>(A,B,nullptr,C,M,N,K,nullptr,nullptr); break;
        case 4: gemm_tf32_kernel<4><<<grid,256,GEMM_SMEM_BYTES>>>(A,B,aux,C,M,N,K,pz,px); break;
        default: gemm_tf32_kernel<3><<<grid,256,GEMM_SMEM_BYTES>>>(A,B,aux,C,M,N,K,nullptr,nullptr); break;
    }
}

static void run_block(float* tptr, int i, int early, int fusePos,
    const float* ln1s, const float* ln1b, const float* qkvw, const float* projw,
    const float* ln2s, const float* ln2b, const float* mlp1w, const float* mlp2w,
    float* hbuf, float* qkvbuf, float* obuf, float* hidbuf,
    const float* posz, const float* posx)
{
    ln_kernel<<<MTOT,128>>>(tptr, hbuf, ln1s + i*384, ln1b + i*384);
    run_gemm(hbuf, qkvw + (size_t)i*384*1152, nullptr, qkvbuf, MTOT, 1152, 384, 0);
    if (early) {
        attn_mma_kernel<64> <<<GBN*NHD,256,ATTN_SMEM(64)>>>(qkvbuf, obuf, 0);
        attn_mma_kernel<256><<<GBN*NHD,256,ATTN_SMEM(256)>>>(qkvbuf, obuf, NTZ);
    } else {
        attn_mma_kernel<320><<<GBN*NHD,256,ATTN_SMEM(320)>>>(qkvbuf, obuf, 0);
    }
    run_gemm(obuf, projw + (size_t)i*384*384, tptr, tptr, MTOT, 384, 384, 3);
    ln_kernel<<<MTOT,128>>>(tptr, hbuf, ln2s + i*384, ln2b + i*384);
    run_gemm(hbuf, mlp1w + (size_t)i*384*1536, nullptr, hidbuf, MTOT, 1536, 384, 2);
    if (fusePos)
        run_gemm(hidbuf, mlp2w + (size_t)i*1536*384, tptr, tptr, MTOT, 384, 1536, 4, posz, posx);
    else
        run_gemm(hidbuf, mlp2w + (size_t)i*1536*384, tptr, tptr, MTOT, 384, 1536, 3);
}

extern "C" void kernel_launch(void* const* d_in, const int* in_sizes, int n_in,
                              void* d_out, int out_size)
{
    const float* z      = (const float*)d_in[0];
    const float* x      = (const float*)d_in[1];
    const float* cs18   = (const float*)d_in[2];
    const float* cs16   = (const float*)d_in[3];
    const float* cs14   = (const float*)d_in[4];
    const float* csMP   = (const float*)d_in[5];
    const float* patchw = (const float*)d_in[6];
    const float* patchb = (const float*)d_in[7];
    const float* posz   = (const float*)d_in[8];
    const float* posx   = (const float*)d_in[9];
    const float* ln1s   = (const float*)d_in[10];
    const float* ln1b   = (const float*)d_in[11];
    const float* qkvw   = (const float*)d_in[12];
    const float* projw  = (const float*)d_in[13];
    const float* ln2s   = (const float*)d_in[14];
    const float* ln2b   = (const float*)d_in[15];
    const float* mlp1w  = (const float*)d_in[16];
    const float* mlp2w  = (const float*)d_in[17];
    const float* norms  = (const float*)d_in[18];
    const float* normb  = (const float*)d_in[19];
    float* out = (float*)d_out;

    float *p_t, *p_qkv, *p_h, *p_o, *p_hid, *p_col, *p_patchw_t;
    cudaGetSymbolAddress((void**)&p_t, g_t);
    cudaGetSymbolAddress((void**)&p_qkv, g_qkv);
    cudaGetSymbolAddress((void**)&p_h, g_h);
    cudaGetSymbolAddress((void**)&p_o, g_o);
    cudaGetSymbolAddress((void**)&p_hid, g_hidden);
    cudaGetSymbolAddress((void**)&p_col, g_col);
    cudaGetSymbolAddress((void**)&p_patchw_t, g_patchw_t);

    cudaFuncSetAttribute(attn_mma_kernel<64>,  cudaFuncAttributeMaxDynamicSharedMemorySize, ATTN_SMEM(64));
    cudaFuncSetAttribute(attn_mma_kernel<256>, cudaFuncAttributeMaxDynamicSharedMemorySize, ATTN_SMEM(256));
    cudaFuncSetAttribute(attn_mma_kernel<320>, cudaFuncAttributeMaxDynamicSharedMemorySize, ATTN_SMEM(320));
    cudaFuncSetAttribute(gemm_tf32_kernel<0>, cudaFuncAttributeMaxDynamicSharedMemorySize, GEMM_SMEM_BYTES);
    cudaFuncSetAttribute(gemm_tf32_kernel<1>, cudaFuncAttributeMaxDynamicSharedMemorySize, GEMM_SMEM_BYTES);
    cudaFuncSetAttribute(gemm_tf32_kernel<2>, cudaFuncAttributeMaxDynamicSharedMemorySize, GEMM_SMEM_BYTES);
    cudaFuncSetAttribute(gemm_tf32_kernel<3>, cudaFuncAttributeMaxDynamicSharedMemorySize, GEMM_SMEM_BYTES);
    cudaFuncSetAttribute(gemm_tf32_kernel<4>, cudaFuncAttributeMaxDynamicSharedMemorySize, GEMM_SMEM_BYTES);
    cudaFuncSetAttribute(conv_all_kernel, cudaFuncAttributeMaxDynamicSharedMemorySize, CONV_ALL_SMEM);

    // launch 1: merged multi-scale convs
    conv_all_kernel<<<CONV_ALL_GRID,256,CONV_ALL_SMEM>>>(x, cs18, cs16, cs14);
    // launch 2: pool + gram + per-batch argsort
    pool_gram_sort_kernel<<<16,256>>>(csMP, out + OFF_OV, out + OFF_OI);
    // launch 3: im2col z + im2col x + patch weight transpose
    prep_kernel<<<PREP_TOTAL/256,256>>>(z, x, patchw, p_col);
    // launch 4: patch-embed GEMM (profiled slot)
    run_gemm(p_col, p_patchw_t, patchb, p_t, MTOT, 384, 768, 1);

    // merged flat + channel-scaled copies for z and x
    copy_all_kernel<<<(ZQ + XQ + 255)/256, 256>>>(z, x, out);

    // early transformer blocks (segment-local attention); block 1 fuses +pos
    run_block(p_t, 0, 1, 0, ln1s, ln1b, qkvw, projw, ln2s, ln2b,
              mlp1w, mlp2w, p_h, p_qkv, p_o, p_hid, posz, posx);
    run_block(p_t, 1, 1, 1, ln1s, ln1b, qkvw, projw, ln2s, ln2b,
              mlp1w, mlp2w, p_h, p_qkv, p_o, p_hid, posz, posx);

    // late blocks (full attention)
    for (int i = 2; i < 4; i++)
        run_block(p_t, i, 0, 0, ln1s, ln1b, qkvw, projw, ln2s, ln2b,
                  mlp1w, mlp2w, p_h, p_qkv, p_o, p_hid, posz, posx);

    // group-sum + final LayerNorm
    final_kernel<<<16*NTOT, 128>>>(norms, normb, out + OFF_OUT);
}

// round 16
// speedup vs baseline: 1.0727x; 1.0062x over previous
#include <cuda_runtime.h>
#include <cuda_bf16.h>
#include <math.h>
#include <stdint.h>

// ---------------------------------------------------------------------------
// Problem constants
// ---------------------------------------------------------------------------
#define BB    16
#define CHN   16
#define HZ    128
#define HX    256
#define EMB   384
#define NHD   6
#define NGRP  5
#define NTZ   64
#define NTX   256
#define GBN   80
#define NTOT  320
#define MTOT  25600    // GBN * NTOT

#define OFF_OUT  0
#define OFF_ZF   1966080
#define OFF_XF   6160384
#define OFF_ZCG  22937600
#define OFF_XCG  27131904
#define OFF_OV   43909120
#define OFF_OI   43909376

// ---------------------------------------------------------------------------
// Device scratch
// ---------------------------------------------------------------------------
__device__ float g_conv18[16*16*14*14];
__device__ float g_conv16[16*16*16*16];
__device__ float g_conv14[16*16*18*18];
__device__ float g_wbuf[256];
__device__ int   g_order[256];
__device__ float g_t[25600*384];        // unified token buffer (concat layout)
__device__ float g_h[25600*384];
__device__ float g_qkv[25600*1152];
__device__ float g_o[25600*384];
__device__ float g_hidden[25600*1536];
__device__ float g_col[25600*768];
__device__ float g_patchw_t[768*384];

// ---------------------------------------------------------------------------
// PTX helpers
// ---------------------------------------------------------------------------
__device__ __forceinline__ void mma1688_tf32(float* d, const uint32_t* a, const uint32_t* b) {
    asm volatile("mma.sync.aligned.m16n8k8.row.col.f32.tf32.tf32.f32 "
        "{%0,%1,%2,%3},{%4,%5,%6,%7},{%8,%9},{%0,%1,%2,%3};"
        : "+f"(d[0]),"+f"(d[1]),"+f"(d[2]),"+f"(d[3])
        : "r"(a[0]),"r"(a[1]),"r"(a[2]),"r"(a[3]), "r"(b[0]),"r"(b[1]));
}
__device__ __forceinline__ void cp16(void* dst_smem, const void* src) {
    uint32_t d = (uint32_t)__cvta_generic_to_shared(dst_smem);
    asm volatile("cp.async.cg.shared.global [%0],[%1],16;" :: "r"(d), "l"(src));
}
__device__ __forceinline__ void ldsm4(uint32_t* d, uint32_t a) {
    asm volatile("ldmatrix.sync.aligned.m8n8.x4.shared.b16 {%0,%1,%2,%3},[%4];"
        : "=r"(d[0]),"=r"(d[1]),"=r"(d[2]),"=r"(d[3]) : "r"(a));
}
__device__ __forceinline__ uint32_t f2tfr(float f) {
    uint32_t u;
    asm("cvt.rna.tf32.f32 %0, %1;" : "=r"(u) : "f"(f));
    return u;
}
__device__ __forceinline__ float tf32r(float f) {
    return __uint_as_float(f2tfr(f));
}

__device__ __forceinline__ float gelu_f(float x)
{
    float x3 = x*x*x;
    return 0.5f*x*(1.0f + tanhf(0.7978845608028654f*(x + 0.044715f*x3)));
}

// ---------------------------------------------------------------------------
// TF32 tensor-core GEMM: same 128x128x32 CTA tile / 3-stage cp.async pipeline
// as the proven R13 config, but 512 threads = 16 warps (4Mx4N, warp tile
// 32x32) so 2 CTAs/SM = 32 warps/SM for latency hiding. Identical per-CTA
// memory traffic; identical per-element accumulation order.
// EPI: 0 none, 1 +bias, 2 gelu, 3 +residual, 4 +residual +pos
// ---------------------------------------------------------------------------
#define AS_W   36
#define BS_W   136
#define AS_TILE (128*AS_W)
#define BS_TILE (32*BS_W)
#define GEMM_SMEM_BYTES ((3*AS_TILE + 3*BS_TILE)*4)

template<int EPI>
__global__ void __launch_bounds__(512,2) gemm_tf32_kernel(
    const float* __restrict__ A, const float* __restrict__ B,
    const float* __restrict__ aux, float* __restrict__ C,
    int M, int N, int K,
    const float* __restrict__ pz, const float* __restrict__ px)
{
    extern __shared__ uint32_t sm_[];
    uint32_t* AsBase = sm_;
    uint32_t* BsBase = sm_ + 3*AS_TILE;

    const int tid  = threadIdx.x;
    const int warp = tid >> 5, lane = tid & 31;
    const int wm = (warp & 3) * 32;
    const int wn = (warp >> 2) * 32;
    const int mBase = blockIdx.y * 128, nBase = blockIdx.x * 128;
    const int gid = lane >> 2, tg = lane & 3;
    const int KT = K >> 5;

    // loads: A 128x32 = 1024 float4 chunks (2/thread); B 32x128 = 1024 (2/thread)
    const int arow0 = tid >> 3, acof0 = (tid & 7) * 4;   // chunk1: row+64, same col
    const int bkr0  = tid >> 5, bnc0  = (tid & 31) * 4;  // chunk1: k+16,  same col

    const int lmRow = wm + (lane & 15);
    const int lmCol = (lane >> 4) * 4;
    const uint32_t aAddr0 = (uint32_t)__cvta_generic_to_shared(
        AsBase + lmRow*AS_W + lmCol);

    float acc[2][4][4];
    #pragma unroll
    for (int i = 0; i < 2; i++)
        #pragma unroll
        for (int j = 0; j < 4; j++)
            #pragma unroll
            for (int e = 0; e < 4; e++) acc[i][j][e] = 0.f;

    auto issue = [&](int kt, int buf) {
        int k0 = kt * 32;
        uint32_t* as = AsBase + buf*AS_TILE;
        uint32_t* bs = BsBase + buf*BS_TILE;
        cp16(as + arow0*AS_W + acof0,
             A + (size_t)(mBase + arow0)*K + k0 + acof0);
        cp16(as + (arow0+64)*AS_W + acof0,
             A + (size_t)(mBase + arow0 + 64)*K + k0 + acof0);
        cp16(bs + bkr0*BS_W + bnc0,
             B + (size_t)(k0 + bkr0)*N + nBase + bnc0);
        cp16(bs + (bkr0+16)*BS_W + bnc0,
             B + (size_t)(k0 + bkr0 + 16)*N + nBase + bnc0);
        asm volatile("cp.async.commit_group;");
    };

    issue(0, 0);
    issue(1, 1);

    for (int kt = 0; kt < KT; kt++) {
        if (kt + 1 < KT) asm volatile("cp.async.wait_group 1;");
        else             asm volatile("cp.async.wait_group 0;");
        __syncthreads();
        if (kt + 2 < KT) issue(kt + 2, (kt + 2) % 3);

        const int stg = kt % 3;
        const uint32_t aAddr = aAddr0 + stg*AS_TILE*4;
        const uint32_t* bs = BsBase + stg*BS_TILE;
        #pragma unroll
        for (int ks = 0; ks < 32; ks += 8) {
            uint32_t a[2][4], b[4][2];
            #pragma unroll
            for (int mt = 0; mt < 2; mt++)
                ldsm4(a[mt], aAddr + (mt*16*AS_W + ks)*4);
            #pragma unroll
            for (int nt = 0; nt < 4; nt++) {
                b[nt][0] = bs[(ks + tg    )*BS_W + wn + nt*8 + gid];
                b[nt][1] = bs[(ks + tg + 4)*BS_W + wn + nt*8 + gid];
            }
            #pragma unroll
            for (int mt = 0; mt < 2; mt++)
                #pragma unroll
                for (int nt = 0; nt < 4; nt++)
                    mma1688_tf32(acc[mt][nt], a[mt], b[nt]);
        }
    }

    #pragma unroll
    for (int mt = 0; mt < 2; mt++) {
        #pragma unroll
        for (int nt = 0; nt < 4; nt++) {
            #pragma unroll
            for (int half = 0; half < 2; half++) {
                int m = mBase + wm + mt*16 + gid + half*8;
                int n = nBase + wn + nt*8 + tg*2;
                float v0 = acc[mt][nt][half*2];
                float v1 = acc[mt][nt][half*2+1];
                if (EPI == 1) { v0 += aux[n]; v1 += aux[n+1]; }
                else if (EPI == 2) { v0 = gelu_f(v0); v1 = gelu_f(v1); }
                else if (EPI == 3) {
                    const float2 rr = *(const float2*)(aux + (size_t)m*N + n);
                    v0 += rr.x; v1 += rr.y;
                } else if (EPI == 4) {
                    const float2 rr = *(const float2*)(aux + (size_t)m*N + n);
                    v0 += rr.x; v1 += rr.y;
                    int ntok = m % NTOT;
                    const float* pp = (ntok < NTZ)
                        ? (pz + (size_t)ntok*384 + n)
                        : (px + (size_t)(ntok-NTZ)*384 + n);
                    v0 += pp[0]; v1 += pp[1];
                }
                *(float2*)(C + (size_t)m*N + n) = make_float2(v0, v1);
            }
        }
    }
}

// ---------------------------------------------------------------------------
// Tensor-core flash attention (tf32 mma, online softmax) — unchanged
// ---------------------------------------------------------------------------
template<int N>
__global__ void __launch_bounds__(256) attn_mma_kernel(
    const float* __restrict__ qkv, float* __restrict__ o, int rowOff)
{
    extern __shared__ float smf[];
    float* Ks = smf;                          // N*68
    float* Vt = smf + N*68;                   // 64*(N+4)
    float* Ps = smf + N*68 + 64*(N+4);        // 8 * 16*20

    const int gb = blockIdx.x / NHD, h = blockIdx.x % NHD;
    const int tid = threadIdx.x;
    const size_t base = (size_t)gb * NTOT + rowOff;
    const int VLD = N + 4;

    for (int idx = tid; idx < N*64; idx += 256) {
        int n = idx >> 6, d = idx & 63;
        const float* p = qkv + (base + n)*1152 + h*64 + d;
        Ks[n*68 + d]   = tf32r(p[384]);
        Vt[d*VLD + n]  = tf32r(p[768]);
    }
    __syncthreads();

    const int warp = tid >> 5, lane = tid & 31;
    const int gid = lane >> 2, tg = lane & 3;
    float* Pw = Ps + warp * (16*20);
    constexpr int NT = N / 16;

    for (int mt = warp; mt < NT; mt += 8) {
        int m0 = mt * 16;
        uint32_t aq[8][4];
        const float* q0 = qkv + (base + m0 + gid)*1152 + h*64;
        const float* q1 = q0 + 8*1152;
        #pragma unroll
        for (int c = 0; c < 8; c++) {
            aq[c][0] = f2tfr(q0[c*8 + tg]     * 0.125f);
            aq[c][1] = f2tfr(q1[c*8 + tg]     * 0.125f);
            aq[c][2] = f2tfr(q0[c*8 + tg + 4] * 0.125f);
            aq[c][3] = f2tfr(q1[c*8 + tg + 4] * 0.125f);
        }

        float o_[8][4];
        #pragma unroll
        for (int j = 0; j < 8; j++)
            #pragma unroll
            for (int e = 0; e < 4; e++) o_[j][e] = 0.f;
        float mx0 = -1e30f, mx1 = -1e30f, l0 = 0.f, l1 = 0.f;

        for (int n0 = 0; n0 < N; n0 += 16) {
            float s[2][4];
            #pragma unroll
            for (int j = 0; j < 2; j++)
                #pragma unroll
                for (int e = 0; e < 4; e++) s[j][e] = 0.f;

            #pragma unroll
            for (int c = 0; c < 8; c++) {
                #pragma unroll
                for (int j = 0; j < 2; j++) {
                    uint32_t b[2];
                    const float* kr = Ks + (n0 + j*8 + gid)*68 + c*8;
                    b[0] = __float_as_uint(kr[tg]);
                    b[1] = __float_as_uint(kr[tg + 4]);
                    mma1688_tf32(s[j], aq[c], b);
                }
            }

            float cm0 = fmaxf(fmaxf(s[0][0], s[0][1]), fmaxf(s[1][0], s[1][1]));
            float cm1 = fmaxf(fmaxf(s[0][2], s[0][3]), fmaxf(s[1][2], s[1][3]));
            cm0 = fmaxf(cm0, __shfl_xor_sync(~0u, cm0, 1));
            cm0 = fmaxf(cm0, __shfl_xor_sync(~0u, cm0, 2));
            cm1 = fmaxf(cm1, __shfl_xor_sync(~0u, cm1, 1));
            cm1 = fmaxf(cm1, __shfl_xor_sync(~0u, cm1, 2));
            float mn0 = fmaxf(mx0, cm0), mn1 = fmaxf(mx1, cm1);
            float sc0 = __expf(mx0 - mn0), sc1 = __expf(mx1 - mn1);
            mx0 = mn0; mx1 = mn1;
            #pragma unroll
            for (int j = 0; j < 2; j++) {
                s[j][0] = __expf(s[j][0] - mn0);
                s[j][1] = __expf(s[j][1] - mn0);
                s[j][2] = __expf(s[j][2] - mn1);
                s[j][3] = __expf(s[j][3] - mn1);
            }
            float rs0 = s[0][0] + s[0][1] + s[1][0] + s[1][1];
            float rs1 = s[0][2] + s[0][3] + s[1][2] + s[1][3];
            rs0 += __shfl_xor_sync(~0u, rs0, 1);
            rs0 += __shfl_xor_sync(~0u, rs0, 2);
            rs1 += __shfl_xor_sync(~0u, rs1, 1);
            rs1 += __shfl_xor_sync(~0u, rs1, 2);
            l0 = l0*sc0 + rs0;
            l1 = l1*sc1 + rs1;
            #pragma unroll
            for (int j = 0; j < 8; j++) {
                o_[j][0] *= sc0; o_[j][1] *= sc0;
                o_[j][2] *= sc1; o_[j][3] *= sc1;
            }

            #pragma unroll
            for (int j = 0; j < 2; j++) {
                Pw[gid*20     + j*8 + 2*tg]     = __uint_as_float(f2tfr(s[j][0]));
                Pw[gid*20     + j*8 + 2*tg + 1] = __uint_as_float(f2tfr(s[j][1]));
                Pw[(gid+8)*20 + j*8 + 2*tg]     = __uint_as_float(f2tfr(s[j][2]));
                Pw[(gid+8)*20 + j*8 + 2*tg + 1] = __uint_as_float(f2tfr(s[j][3]));
            }
            __syncwarp();
            #pragma unroll
            for (int kk = 0; kk < 2; kk++) {
                uint32_t ap[4];
                ap[0] = __float_as_uint(Pw[gid*20     + kk*8 + tg]);
                ap[1] = __float_as_uint(Pw[(gid+8)*20 + kk*8 + tg]);
                ap[2] = __float_as_uint(Pw[gid*20     + kk*8 + tg + 4]);
                ap[3] = __float_as_uint(Pw[(gid+8)*20 + kk*8 + tg + 4]);
                #pragma unroll
                for (int j = 0; j < 8; j++) {
                    uint32_t bv[2];
                    const float* vr = Vt + (j*8 + gid)*VLD + n0 + kk*8;
                    bv[0] = __float_as_uint(vr[tg]);
                    bv[1] = __float_as_uint(vr[tg + 4]);
                    mma1688_tf32(o_[j], ap, bv);
                }
            }
            __syncwarp();
        }

        float inv0 = 1.f / l0, inv1 = 1.f / l1;
        float* or0 = o + (base + m0 + gid)*384 + h*64;
        float* or1 = or0 + 8*384;
        #pragma unroll
        for (int j = 0; j < 8; j++) {
            *(float2*)(or0 + j*8 + 2*tg) = make_float2(o_[j][0]*inv0, o_[j][1]*inv0);
            *(float2*)(or1 + j*8 + 2*tg) = make_float2(o_[j][2]*inv1, o_[j][3]*inv1);
        }
    }
}

#define ATTN_SMEM(N) ((N*68 + 64*(N+4) + 8*16*20)*4)

// ---------------------------------------------------------------------------
// Merged multi-scale conv (one launch; block ranges dispatch the 3 scales)
// ---------------------------------------------------------------------------
template<int KS, int OHW, int POS>
__device__ __forceinline__ void conv_body(
    const float* __restrict__ x, const float* __restrict__ w,
    float* __restrict__ out, int blk)
{
    extern __shared__ float sp[];
    constexpr int PSZ = CHN*KS*KS;
    constexpr int NPB = (OHW*OHW + POS - 1) / POS;
    const int b = blk / NPB;
    const int pos0 = (blk % NPB) * POS;

    #pragma unroll
    for (int q = 0; q < POS; q++) {
        int pos = pos0 + q;
        if (pos >= OHW*OHW) break;
        int oy = pos / OHW, ox = pos % OHW;
        const float* xb = x + ((size_t)(b*CHN))*HX*HX + (size_t)oy*KS*HX + ox*KS;
        for (int p = threadIdx.x; p < PSZ; p += 256) {
            int ci = p / (KS*KS); int pp = p % (KS*KS);
            int ky = pp / KS, kx = pp % KS;
            sp[q*PSZ + p] = xb[((size_t)ci*HX + ky)*HX + kx];
        }
    }
    __syncthreads();

    const int co = threadIdx.x >> 4, ln = threadIdx.x & 15;
    const float* wp = w + (size_t)co * PSZ;
    float acc[POS];
    #pragma unroll
    for (int q = 0; q < POS; q++) acc[q] = 0.f;

    for (int p = ln; p < PSZ; p += 16) {
        float wv = wp[p];
        #pragma unroll
        for (int q = 0; q < POS; q++)
            acc[q] = fmaf(sp[q*PSZ + p], wv, acc[q]);
    }

    #pragma unroll
    for (int q = 0; q < POS; q++) {
        float a = acc[q];
        #pragma unroll
        for (int off = 8; off; off >>= 1)
            a += __shfl_xor_sync(0xffffffffu, a, off, 16);
        int pos = pos0 + q;
        if (ln == 0 && pos < OHW*OHW)
            out[(size_t)(b*CHN+co)*OHW*OHW + pos] = a;
    }
}

__global__ void __launch_bounds__(256) conv_all_kernel(
    const float* __restrict__ x, const float* __restrict__ cs18,
    const float* __restrict__ cs16, const float* __restrict__ cs14)
{
    int blk = blockIdx.x;
    if (blk < 16*28)           conv_body<18,14,7>(x, cs18, g_conv18, blk);
    else if (blk < 16*28+16*32) conv_body<16,16,8>(x, cs16, g_conv16, blk - 16*28);
    else                        conv_body<14,18,9>(x, cs14, g_conv14, blk - 16*28 - 16*32);
}
#define CONV_ALL_SMEM (7*CHN*18*18*4)
#define CONV_ALL_GRID (16*28 + 16*32 + 16*36)

// ---------------------------------------------------------------------------
// Merged pool + gram + per-batch argsort (one block per batch)
// ---------------------------------------------------------------------------
__global__ void __launch_bounds__(256) pool_gram_sort_kernel(
    const float* __restrict__ W, float* __restrict__ out_vals, float* __restrict__ out_idx)
{
    __shared__ float tok[77*16];
    __shared__ float ms[77*16];
    __shared__ float cm[256];
    __shared__ float nrm[16];
    __shared__ float wv[16];
    int b = blockIdx.x, tid = threadIdx.x;

    for (int i = tid; i < 77*16; i += 256) {
        int c = i & 15, l = i >> 4;
        float av = 0.f, mx = -1e30f;
        if (l < 16) {
            int li = l, py = li/4, px = li%4;
            const float* cb = g_conv18 + (size_t)(b*16+c)*14*14;
            for (int ky=0; ky<3; ky++) for (int kx=0; kx<3; kx++) {
                float v = cb[(py*3+ky)*14 + (px*3+kx)];
                av += v; mx = fmaxf(mx, v);
            }
        } else if (l < 41) {
            int li = l-16, py = li/5, px = li%5;
            const float* cb = g_conv16 + (size_t)(b*16+c)*16*16;
            for (int ky=0; ky<3; ky++) for (int kx=0; kx<3; kx++) {
                float v = cb[(py*3+ky)*16 + (px*3+kx)];
                av += v; mx = fmaxf(mx, v);
            }
        } else {
            int li = l-41, py = li/6, px = li%6;
            const float* cb = g_conv14 + (size_t)(b*16+c)*18*18;
            for (int ky=0; ky<3; ky++) for (int kx=0; kx<3; kx++) {
                float v = cb[(py*3+ky)*18 + (px*3+kx)];
                av += v; mx = fmaxf(mx, v);
            }
        }
        tok[i] = av*(1.f/9.f) + mx;
    }
    __syncthreads();

    for (int i = tid; i < 77*16; i += 256) {
        int l = i >> 4, d = i & 15;
        float s = 0.f;
        #pragma unroll
        for (int c = 0; c < 16; c++) s += tok[l*16+c] * W[c*16+d];
        ms[i] = s;
    }
    __syncthreads();
    {
        int c = tid >> 4, d = tid & 15;
        float s = 0.f;
        for (int l = 0; l < 77; l++) s += ms[l*16+c] * ms[l*16+d];
        cm[tid] = (c == d) ? 0.f : s;
    }
    __syncthreads();
    if (tid < 16) {
        float s = 0.f;
        #pragma unroll
        for (int d = 0; d < 16; d++) { float v = cm[tid*16+d]; s += v*v; }
        nrm[tid] = fmaxf(sqrtf(s), 1e-12f);
    }
    __syncthreads();
    float v = cm[tid] / nrm[tid >> 4];
    __syncthreads();
    cm[tid] = v;
    __syncthreads();
    if (tid < 16) {
        float s = 0.f;
        #pragma unroll
        for (int d = 0; d < 16; d++) s += fabsf(cm[tid*16+d]);
        g_wbuf[b*16 + tid] = s;
        wv[tid] = s;
    }
    __syncthreads();

    if (tid == 0) {
        float vv[16]; int id[16];
        for (int i = 0; i < 16; i++) { vv[i] = wv[i]; id[i] = i; }
        for (int i = 1; i < 16; i++) {
            float kv = vv[i]; int ki = id[i]; int j = i-1;
            while (j >= 0 && vv[j] < kv) { vv[j+1]=vv[j]; id[j+1]=id[j]; j--; }
            vv[j+1]=kv; id[j+1]=ki;
        }
        for (int i = 0; i < 16; i++) {
            g_order[b*16+i] = id[i];
            out_vals[b*16+i] = vv[i];
            out_idx[b*16+i]  = (float)id[i];
        }
    }
}

// ---------------------------------------------------------------------------
// Merged prep: im2col(z) + im2col(x) + patchw transpose
// ---------------------------------------------------------------------------
#define ZCOLT (NGRP*BB*NTZ*768)
#define XCOLT (NGRP*BB*NTX*768)
#define PWT   (384*768)
#define PREP_TOTAL (ZCOLT + XCOLT + PWT)

__device__ __forceinline__ void im2col_one(
    const float* __restrict__ img, float* __restrict__ A,
    int idx, int NT, int PW, int HW, int rowOff)
{
    int k = idx % 768; int m = idx / 768;
    int n = m % NT; int gb = m / NT;
    int b = gb & 15; int g = gb >> 4;
    int c = k >> 8; int rr = k & 255;
    int ky = rr >> 4, kx = rr & 15;
    int ch = g_order[b*16 + 3*g + c];
    int py = n / PW, px = n % PW;
    float mean, inv;
    if (c == 0)      { mean = 0.485f; inv = 1.f/0.229f; }
    else if (c == 1) { mean = 0.456f; inv = 1.f/0.224f; }
    else             { mean = 0.406f; inv = 1.f/0.225f; }
    float v = img[((size_t)(b*CHN+ch)*HW + py*16+ky)*HW + px*16+kx];
    size_t row = (size_t)gb*NTOT + rowOff + n;
    A[row*768 + k] = (v - mean) * inv;
}

__global__ void prep_kernel(const float* __restrict__ z, const float* __restrict__ x,
                            const float* __restrict__ patchw, float* __restrict__ col)
{
    int idx = blockIdx.x*256 + threadIdx.x;
    if (idx < ZCOLT) {
        im2col_one(z, col, idx, NTZ, 8, HZ, 0);
    } else if (idx < ZCOLT + XCOLT) {
        im2col_one(x, col, idx - ZCOLT, NTX, 16, HX, NTZ);
    } else if (idx < PREP_TOTAL) {
        int i = idx - ZCOLT - XCOLT;
        int nrow = i / 768, k = i % 768;
        g_patchw_t[k*384 + nrow] = patchw[i];
    }
}

// ---------------------------------------------------------------------------
// Merged flat + channel-scaled copies for z AND x (float4, range dispatch)
// ---------------------------------------------------------------------------
#define ZQ (BB*CHN*HZ*HZ/4)   // 1,048,576
#define XQ (BB*CHN*HX*HX/4)   // 4,194,304

__global__ void copy_all_kernel(const float* __restrict__ z, const float* __restrict__ x,
                                float* __restrict__ out)
{
    int i4 = blockIdx.x*256 + threadIdx.x;
    if (i4 < ZQ) {
        int bc = i4 / (HZ*HZ/4);
        float w = g_wbuf[bc];
        float4 v = ((const float4*)z)[i4];
        ((float4*)(out + OFF_ZF))[i4] = v;
        ((float4*)(out + OFF_ZCG))[i4] = make_float4(v.x*w, v.y*w, v.z*w, v.w*w);
    } else if (i4 < ZQ + XQ) {
        int j4 = i4 - ZQ;
        int bc = j4 / (HX*HX/4);
        float w = g_wbuf[bc];
        float4 v = ((const float4*)x)[j4];
        ((float4*)(out + OFF_XF))[j4] = v;
        ((float4*)(out + OFF_XCG))[j4] = make_float4(v.x*w, v.y*w, v.z*w, v.w*w);
    }
}

// ---------------------------------------------------------------------------
// LayerNorm over E=384
// ---------------------------------------------------------------------------
__global__ void __launch_bounds__(128) ln_kernel(
    const float* __restrict__ in, float* __restrict__ out,
    const float* __restrict__ s, const float* __restrict__ bb)
{
    int row = blockIdx.x, tid = threadIdx.x;
    const float* ip = in + (size_t)row*384;
    float v0 = ip[tid], v1 = ip[tid+128], v2 = ip[tid+256];
    __shared__ float red[4];
    float loc = v0 + v1 + v2;
    #pragma unroll
    for (int o = 16; o; o >>= 1) loc += __shfl_xor_sync(~0u, loc, o);
    int w = tid >> 5, ln = tid & 31;
    if (ln == 0) red[w] = loc;
    __syncthreads();
    float mu = (red[0]+red[1]+red[2]+red[3]) * (1.f/384.f);
    float d0 = v0-mu, d1 = v1-mu, d2 = v2-mu;
    float loc2 = d0*d0 + d1*d1 + d2*d2;
    #pragma unroll
    for (int o = 16; o; o >>= 1) loc2 += __shfl_xor_sync(~0u, loc2, o);
    __syncthreads();
    if (ln == 0) red[w] = loc2;
    __syncthreads();
    float var = (red[0]+red[1]+red[2]+red[3]) * (1.f/384.f);
    float rs = rsqrtf(var + 1e-6f);
    float* op = out + (size_t)row*384;
    op[tid]     = d0*rs*s[tid]     + bb[tid];
    op[tid+128] = d1*rs*s[tid+128] + bb[tid+128];
    op[tid+256] = d2*rs*s[tid+256] + bb[tid+256];
}

// ---------------------------------------------------------------------------
// group-sum + final LayerNorm
// ---------------------------------------------------------------------------
__global__ void __launch_bounds__(128) final_kernel(
    const float* __restrict__ s, const float* __restrict__ bb, float* __restrict__ out)
{
    int row = blockIdx.x;
    int b = row / NTOT, n = row % NTOT;
    int tid = threadIdx.x;
    float v[3];
    #pragma unroll
    for (int i = 0; i < 3; i++) {
        int e = tid + 128*i;
        float a = 0.f;
        #pragma unroll
        for (int g = 0; g < 5; g++)
            a += g_t[(((size_t)(g*16+b)*NTOT + n)*384) + e];
        v[i] = a;
    }
    __shared__ float red[4];
    float loc = v[0]+v[1]+v[2];
    #pragma unroll
    for (int o = 16; o; o >>= 1) loc += __shfl_xor_sync(~0u, loc, o);
    int w = tid >> 5, ln = tid & 31;
    if (ln == 0) red[w] = loc;
    __syncthreads();
    float mu = (red[0]+red[1]+red[2]+red[3]) * (1.f/384.f);
    float d0 = v[0]-mu, d1 = v[1]-mu, d2 = v[2]-mu;
    float loc2 = d0*d0 + d1*d1 + d2*d2;
    #pragma unroll
    for (int o = 16; o; o >>= 1) loc2 += __shfl_xor_sync(~0u, loc2, o);
    __syncthreads();
    if (ln == 0) red[w] = loc2;
    __syncthreads();
    float var = (red[0]+red[1]+red[2]+red[3]) * (1.f/384.f);
    float rs = rsqrtf(var + 1e-6f);
    float* op = out + (size_t)row*384;
    op[tid]     = d0*rs*s[tid]     + bb[tid];
    op[tid+128] = d1*rs*s[tid+128] + bb[tid+128];
    op[tid+256] = d2*rs*s[tid+256] + bb[tid+256];
}

// ---------------------------------------------------------------------------
// Host side
// ---------------------------------------------------------------------------
static void run_gemm(const float* A, const float* B, const float* aux, float* C,
                     int M, int N, int K, int epi,
                     const float* pz = nullptr, const float* px = nullptr)
{
    dim3 grid(N/128, M/128);
    switch (epi) {
        case 0: gemm_tf32_kernel<0><<<grid,512,GEMM_SMEM_BYTES>>>(A,B,nullptr,C,M,N,K,nullptr,nullptr); break;
        case 1: gemm_tf32_kernel<1><<<grid,512,GEMM_SMEM_BYTES>>>(A,B,aux,C,M,N,K,nullptr,nullptr); break;
        case 2: gemm_tf32_kernel<2><<<grid,512,GEMM_SMEM_BYTES>>>(A,B,nullptr,C,M,N,K,nullptr,nullptr); break;
        case 4: gemm_tf32_kernel<4><<<grid,512,GEMM_SMEM_BYTES>>>(A,B,aux,C,M,N,K,pz,px); break;
        default: gemm_tf32_kernel<3><<<grid,512,GEMM_SMEM_BYTES>>>(A,B,aux,C,M,N,K,nullptr,nullptr); break;
    }
}

static void run_block(float* tptr, int i, int early, int fusePos,
    const float* ln1s, const float* ln1b, const float* qkvw, const float* projw,
    const float* ln2s, const float* ln2b, const float* mlp1w, const float* mlp2w,
    float* hbuf, float* qkvbuf, float* obuf, float* hidbuf,
    const float* posz, const float* posx)
{
    ln_kernel<<<MTOT,128>>>(tptr, hbuf, ln1s + i*384, ln1b + i*384);
    run_gemm(hbuf, qkvw + (size_t)i*384*1152, nullptr, qkvbuf, MTOT, 1152, 384, 0);
    if (early) {
        attn_mma_kernel<64> <<<GBN*NHD,256,ATTN_SMEM(64)>>>(qkvbuf, obuf, 0);
        attn_mma_kernel<256><<<GBN*NHD,256,ATTN_SMEM(256)>>>(qkvbuf, obuf, NTZ);
    } else {
        attn_mma_kernel<320><<<GBN*NHD,256,ATTN_SMEM(320)>>>(qkvbuf, obuf, 0);
    }
    run_gemm(obuf, projw + (size_t)i*384*384, tptr, tptr, MTOT, 384, 384, 3);
    ln_kernel<<<MTOT,128>>>(tptr, hbuf, ln2s + i*384, ln2b + i*384);
    run_gemm(hbuf, mlp1w + (size_t)i*384*1536, nullptr, hidbuf, MTOT, 1536, 384, 2);
    if (fusePos)
        run_gemm(hidbuf, mlp2w + (size_t)i*1536*384, tptr, tptr, MTOT, 384, 1536, 4, posz, posx);
    else
        run_gemm(hidbuf, mlp2w + (size_t)i*1536*384, tptr, tptr, MTOT, 384, 1536, 3);
}

extern "C" void kernel_launch(void* const* d_in, const int* in_sizes, int n_in,
                              void* d_out, int out_size)
{
    const float* z      = (const float*)d_in[0];
    const float* x      = (const float*)d_in[1];
    const float* cs18   = (const float*)d_in[2];
    const float* cs16   = (const float*)d_in[3];
    const float* cs14   = (const float*)d_in[4];
    const float* csMP   = (const float*)d_in[5];
    const float* patchw = (const float*)d_in[6];
    const float* patchb = (const float*)d_in[7];
    const float* posz   = (const float*)d_in[8];
    const float* posx   = (const float*)d_in[9];
    const float* ln1s   = (const float*)d_in[10];
    const float* ln1b   = (const float*)d_in[11];
    const float* qkvw   = (const float*)d_in[12];
    const float* projw  = (const float*)d_in[13];
    const float* ln2s   = (const float*)d_in[14];
    const float* ln2b   = (const float*)d_in[15];
    const float* mlp1w  = (const float*)d_in[16];
    const float* mlp2w  = (const float*)d_in[17];
    const float* norms  = (const float*)d_in[18];
    const float* normb  = (const float*)d_in[19];
    float* out = (float*)d_out;

    float *p_t, *p_qkv, *p_h, *p_o, *p_hid, *p_col, *p_patchw_t;
    cudaGetSymbolAddress((void**)&p_t, g_t);
    cudaGetSymbolAddress((void**)&p_qkv, g_qkv);
    cudaGetSymbolAddress((void**)&p_h, g_h);
    cudaGetSymbolAddress((void**)&p_o, g_o);
    cudaGetSymbolAddress((void**)&p_hid, g_hidden);
    cudaGetSymbolAddress((void**)&p_col, g_col);
    cudaGetSymbolAddress((void**)&p_patchw_t, g_patchw_t);

    cudaFuncSetAttribute(attn_mma_kernel<64>,  cudaFuncAttributeMaxDynamicSharedMemorySize, ATTN_SMEM(64));
    cudaFuncSetAttribute(attn_mma_kernel<256>, cudaFuncAttributeMaxDynamicSharedMemorySize, ATTN_SMEM(256));
    cudaFuncSetAttribute(attn_mma_kernel<320>, cudaFuncAttributeMaxDynamicSharedMemorySize, ATTN_SMEM(320));
    cudaFuncSetAttribute(gemm_tf32_kernel<0>, cudaFuncAttributeMaxDynamicSharedMemorySize, GEMM_SMEM_BYTES);
    cudaFuncSetAttribute(gemm_tf32_kernel<1>, cudaFuncAttributeMaxDynamicSharedMemorySize, GEMM_SMEM_BYTES);
    cudaFuncSetAttribute(gemm_tf32_kernel<2>, cudaFuncAttributeMaxDynamicSharedMemorySize, GEMM_SMEM_BYTES);
    cudaFuncSetAttribute(gemm_tf32_kernel<3>, cudaFuncAttributeMaxDynamicSharedMemorySize, GEMM_SMEM_BYTES);
    cudaFuncSetAttribute(gemm_tf32_kernel<4>, cudaFuncAttributeMaxDynamicSharedMemorySize, GEMM_SMEM_BYTES);
    cudaFuncSetAttribute(conv_all_kernel, cudaFuncAttributeMaxDynamicSharedMemorySize, CONV_ALL_SMEM);

    // launch 1: merged multi-scale convs
    conv_all_kernel<<<CONV_ALL_GRID,256,CONV_ALL_SMEM>>>(x, cs18, cs16, cs14);
    // launch 2: pool + gram + per-batch argsort
    pool_gram_sort_kernel<<<16,256>>>(csMP, out + OFF_OV, out + OFF_OI);
    // launch 3: im2col z + im2col x + patch weight transpose
    prep_kernel<<<PREP_TOTAL/256,256>>>(z, x, patchw, p_col);
    // launch 4: patch-embed GEMM (profiled slot)
    run_gemm(p_col, p_patchw_t, patchb, p_t, MTOT, 384, 768, 1);

    // merged flat + channel-scaled copies for z and x
    copy_all_kernel<<<(ZQ + XQ + 255)/256, 256>>>(z, x, out);

    // early transformer blocks (segment-local attention); block 1 fuses +pos
    run_block(p_t, 0, 1, 0, ln1s, ln1b, qkvw, projw, ln2s, ln2b,
              mlp1w, mlp2w, p_h, p_qkv, p_o, p_hid, posz, posx);
    run_block(p_t, 1, 1, 1, ln1s, ln1b, qkvw, projw, ln2s, ln2b,
              mlp1w, mlp2w, p_h, p_qkv, p_o, p_hid, posz, posx);

    // late blocks (full attention)
    for (int i = 2; i < 4; i++)
        run_block(p_t, i, 0, 0, ln1s, ln1b, qkvw, projw, ln2s, ln2b,
                  mlp1w, mlp2w, p_h, p_qkv, p_o, p_hid, posz, posx);

    // group-sum + final LayerNorm
    final_kernel<<<16*NTOT, 128>>>(norms, normb, out + OFF_OUT);
}

// round 17
// speedup vs baseline: 1.0921x; 1.0181x over previous
#include <cuda_runtime.h>
#include <cuda_bf16.h>
#include <math.h>
#include <stdint.h>

// ---------------------------------------------------------------------------
// Problem constants
// ---------------------------------------------------------------------------
#define BB    16
#define CHN   16
#define HZ    128
#define HX    256
#define EMB   384
#define NHD   6
#define NGRP  5
#define NTZ   64
#define NTX   256
#define GBN   80
#define NTOT  320
#define MTOT  25600    // GBN * NTOT

#define OFF_OUT  0
#define OFF_ZF   1966080
#define OFF_XF   6160384
#define OFF_ZCG  22937600
#define OFF_XCG  27131904
#define OFF_OV   43909120
#define OFF_OI   43909376

// ---------------------------------------------------------------------------
// Device scratch
// ---------------------------------------------------------------------------
__device__ float g_conv18[16*16*14*14];
__device__ float g_conv16[16*16*16*16];
__device__ float g_conv14[16*16*18*18];
__device__ float g_wbuf[256];
__device__ int   g_order[256];
__device__ float g_t[25600*384];        // unified token buffer (concat layout)
__device__ float g_h[25600*384];
__device__ float g_qkv[25600*1152];
__device__ float g_o[25600*384];
__device__ float g_hidden[25600*1536];
__device__ float g_col[25600*768];
__device__ float g_patchw_t[768*384];

// ---------------------------------------------------------------------------
// PTX helpers
// ---------------------------------------------------------------------------
__device__ __forceinline__ void mma1688_tf32(float* d, const uint32_t* a, const uint32_t* b) {
    asm volatile("mma.sync.aligned.m16n8k8.row.col.f32.tf32.tf32.f32 "
        "{%0,%1,%2,%3},{%4,%5,%6,%7},{%8,%9},{%0,%1,%2,%3};"
        : "+f"(d[0]),"+f"(d[1]),"+f"(d[2]),"+f"(d[3])
        : "r"(a[0]),"r"(a[1]),"r"(a[2]),"r"(a[3]), "r"(b[0]),"r"(b[1]));
}
__device__ __forceinline__ void cp16(void* dst_smem, const void* src) {
    uint32_t d = (uint32_t)__cvta_generic_to_shared(dst_smem);
    asm volatile("cp.async.cg.shared.global [%0],[%1],16;" :: "r"(d), "l"(src));
}
__device__ __forceinline__ void ldsm4(uint32_t* d, uint32_t a) {
    asm volatile("ldmatrix.sync.aligned.m8n8.x4.shared.b16 {%0,%1,%2,%3},[%4];"
        : "=r"(d[0]),"=r"(d[1]),"=r"(d[2]),"=r"(d[3]) : "r"(a));
}
__device__ __forceinline__ uint32_t f2tfr(float f) {
    uint32_t u;
    asm("cvt.rna.tf32.f32 %0, %1;" : "=r"(u) : "f"(f));
    return u;
}
__device__ __forceinline__ float tf32r(float f) {
    return __uint_as_float(f2tfr(f));
}

// GELU with hardware tanh (MUFU.TANH, single instruction)
__device__ __forceinline__ float gelu_f(float x)
{
    float u = 0.7978845608028654f * (x + 0.044715f * x * x * x);
    float t;
    asm("tanh.approx.f32 %0, %1;" : "=f"(t) : "f"(u));
    return 0.5f * x * (1.0f + t);
}

// ---------------------------------------------------------------------------
// TF32 tensor-core GEMM: 128x128x32 CTA tile, 3-stage cp.async, 512 threads =
// 16 warps (4Mx4N, warp tile 32x32), 2 CTAs/SM (R16 config — best measured).
// EPI: 0 none, 1 +bias, 2 gelu, 3 +residual, 4 +residual +pos
// ---------------------------------------------------------------------------
#define AS_W   36
#define BS_W   136
#define AS_TILE (128*AS_W)
#define BS_TILE (32*BS_W)
#define GEMM_SMEM_BYTES ((3*AS_TILE + 3*BS_TILE)*4)

template<int EPI>
__global__ void __launch_bounds__(512,2) gemm_tf32_kernel(
    const float* __restrict__ A, const float* __restrict__ B,
    const float* __restrict__ aux, float* __restrict__ C,
    int M, int N, int K,
    const float* __restrict__ pz, const float* __restrict__ px)
{
    extern __shared__ uint32_t sm_[];
    uint32_t* AsBase = sm_;
    uint32_t* BsBase = sm_ + 3*AS_TILE;

    const int tid  = threadIdx.x;
    const int warp = tid >> 5, lane = tid & 31;
    const int wm = (warp & 3) * 32;
    const int wn = (warp >> 2) * 32;
    const int mBase = blockIdx.y * 128, nBase = blockIdx.x * 128;
    const int gid = lane >> 2, tg = lane & 3;
    const int KT = K >> 5;

    const int arow0 = tid >> 3, acof0 = (tid & 7) * 4;
    const int bkr0  = tid >> 5, bnc0  = (tid & 31) * 4;

    const int lmRow = wm + (lane & 15);
    const int lmCol = (lane >> 4) * 4;
    const uint32_t aAddr0 = (uint32_t)__cvta_generic_to_shared(
        AsBase + lmRow*AS_W + lmCol);

    float acc[2][4][4];
    #pragma unroll
    for (int i = 0; i < 2; i++)
        #pragma unroll
        for (int j = 0; j < 4; j++)
            #pragma unroll
            for (int e = 0; e < 4; e++) acc[i][j][e] = 0.f;

    auto issue = [&](int kt, int buf) {
        int k0 = kt * 32;
        uint32_t* as = AsBase + buf*AS_TILE;
        uint32_t* bs = BsBase + buf*BS_TILE;
        cp16(as + arow0*AS_W + acof0,
             A + (size_t)(mBase + arow0)*K + k0 + acof0);
        cp16(as + (arow0+64)*AS_W + acof0,
             A + (size_t)(mBase + arow0 + 64)*K + k0 + acof0);
        cp16(bs + bkr0*BS_W + bnc0,
             B + (size_t)(k0 + bkr0)*N + nBase + bnc0);
        cp16(bs + (bkr0+16)*BS_W + bnc0,
             B + (size_t)(k0 + bkr0 + 16)*N + nBase + bnc0);
        asm volatile("cp.async.commit_group;");
    };

    issue(0, 0);
    issue(1, 1);

    for (int kt = 0; kt < KT; kt++) {
        if (kt + 1 < KT) asm volatile("cp.async.wait_group 1;");
        else             asm volatile("cp.async.wait_group 0;");
        __syncthreads();
        if (kt + 2 < KT) issue(kt + 2, (kt + 2) % 3);

        const int stg = kt % 3;
        const uint32_t aAddr = aAddr0 + stg*AS_TILE*4;
        const uint32_t* bs = BsBase + stg*BS_TILE;
        #pragma unroll
        for (int ks = 0; ks < 32; ks += 8) {
            uint32_t a[2][4], b[4][2];
            #pragma unroll
            for (int mt = 0; mt < 2; mt++)
                ldsm4(a[mt], aAddr + (mt*16*AS_W + ks)*4);
            #pragma unroll
            for (int nt = 0; nt < 4; nt++) {
                b[nt][0] = bs[(ks + tg    )*BS_W + wn + nt*8 + gid];
                b[nt][1] = bs[(ks + tg + 4)*BS_W + wn + nt*8 + gid];
            }
            #pragma unroll
            for (int mt = 0; mt < 2; mt++)
                #pragma unroll
                for (int nt = 0; nt < 4; nt++)
                    mma1688_tf32(acc[mt][nt], a[mt], b[nt]);
        }
    }

    #pragma unroll
    for (int mt = 0; mt < 2; mt++) {
        #pragma unroll
        for (int nt = 0; nt < 4; nt++) {
            #pragma unroll
            for (int half = 0; half < 2; half++) {
                int m = mBase + wm + mt*16 + gid + half*8;
                int n = nBase + wn + nt*8 + tg*2;
                float v0 = acc[mt][nt][half*2];
                float v1 = acc[mt][nt][half*2+1];
                if (EPI == 1) { v0 += aux[n]; v1 += aux[n+1]; }
                else if (EPI == 2) { v0 = gelu_f(v0); v1 = gelu_f(v1); }
                else if (EPI == 3) {
                    const float2 rr = *(const float2*)(aux + (size_t)m*N + n);
                    v0 += rr.x; v1 += rr.y;
                } else if (EPI == 4) {
                    const float2 rr = *(const float2*)(aux + (size_t)m*N + n);
                    v0 += rr.x; v1 += rr.y;
                    int ntok = m % NTOT;
                    const float* pp = (ntok < NTZ)
                        ? (pz + (size_t)ntok*384 + n)
                        : (px + (size_t)(ntok-NTZ)*384 + n);
                    v0 += pp[0]; v1 += pp[1];
                }
                *(float2*)(C + (size_t)m*N + n) = make_float2(v0, v1);
            }
        }
    }
}

// ---------------------------------------------------------------------------
// Tensor-core flash attention (tf32 mma, online softmax) — unchanged
// ---------------------------------------------------------------------------
template<int N>
__global__ void __launch_bounds__(256) attn_mma_kernel(
    const float* __restrict__ qkv, float* __restrict__ o, int rowOff)
{
    extern __shared__ float smf[];
    float* Ks = smf;                          // N*68
    float* Vt = smf + N*68;                   // 64*(N+4)
    float* Ps = smf + N*68 + 64*(N+4);        // 8 * 16*20

    const int gb = blockIdx.x / NHD, h = blockIdx.x % NHD;
    const int tid = threadIdx.x;
    const size_t base = (size_t)gb * NTOT + rowOff;
    const int VLD = N + 4;

    for (int idx = tid; idx < N*64; idx += 256) {
        int n = idx >> 6, d = idx & 63;
        const float* p = qkv + (base + n)*1152 + h*64 + d;
        Ks[n*68 + d]   = tf32r(p[384]);
        Vt[d*VLD + n]  = tf32r(p[768]);
    }
    __syncthreads();

    const int warp = tid >> 5, lane = tid & 31;
    const int gid = lane >> 2, tg = lane & 3;
    float* Pw = Ps + warp * (16*20);
    constexpr int NT = N / 16;

    for (int mt = warp; mt < NT; mt += 8) {
        int m0 = mt * 16;
        uint32_t aq[8][4];
        const float* q0 = qkv + (base + m0 + gid)*1152 + h*64;
        const float* q1 = q0 + 8*1152;
        #pragma unroll
        for (int c = 0; c < 8; c++) {
            aq[c][0] = f2tfr(q0[c*8 + tg]     * 0.125f);
            aq[c][1] = f2tfr(q1[c*8 + tg]     * 0.125f);
            aq[c][2] = f2tfr(q0[c*8 + tg + 4] * 0.125f);
            aq[c][3] = f2tfr(q1[c*8 + tg + 4] * 0.125f);
        }

        float o_[8][4];
        #pragma unroll
        for (int j = 0; j < 8; j++)
            #pragma unroll
            for (int e = 0; e < 4; e++) o_[j][e] = 0.f;
        float mx0 = -1e30f, mx1 = -1e30f, l0 = 0.f, l1 = 0.f;

        for (int n0 = 0; n0 < N; n0 += 16) {
            float s[2][4];
            #pragma unroll
            for (int j = 0; j < 2; j++)
                #pragma unroll
                for (int e = 0; e < 4; e++) s[j][e] = 0.f;

            #pragma unroll
            for (int c = 0; c < 8; c++) {
                #pragma unroll
                for (int j = 0; j < 2; j++) {
                    uint32_t b[2];
                    const float* kr = Ks + (n0 + j*8 + gid)*68 + c*8;
                    b[0] = __float_as_uint(kr[tg]);
                    b[1] = __float_as_uint(kr[tg + 4]);
                    mma1688_tf32(s[j], aq[c], b);
                }
            }

            float cm0 = fmaxf(fmaxf(s[0][0], s[0][1]), fmaxf(s[1][0], s[1][1]));
            float cm1 = fmaxf(fmaxf(s[0][2], s[0][3]), fmaxf(s[1][2], s[1][3]));
            cm0 = fmaxf(cm0, __shfl_xor_sync(~0u, cm0, 1));
            cm0 = fmaxf(cm0, __shfl_xor_sync(~0u, cm0, 2));
            cm1 = fmaxf(cm1, __shfl_xor_sync(~0u, cm1, 1));
            cm1 = fmaxf(cm1, __shfl_xor_sync(~0u, cm1, 2));
            float mn0 = fmaxf(mx0, cm0), mn1 = fmaxf(mx1, cm1);
            float sc0 = __expf(mx0 - mn0), sc1 = __expf(mx1 - mn1);
            mx0 = mn0; mx1 = mn1;
            #pragma unroll
            for (int j = 0; j < 2; j++) {
                s[j][0] = __expf(s[j][0] - mn0);
                s[j][1] = __expf(s[j][1] - mn0);
                s[j][2] = __expf(s[j][2] - mn1);
                s[j][3] = __expf(s[j][3] - mn1);
            }
            float rs0 = s[0][0] + s[0][1] + s[1][0] + s[1][1];
            float rs1 = s[0][2] + s[0][3] + s[1][2] + s[1][3];
            rs0 += __shfl_xor_sync(~0u, rs0, 1);
            rs0 += __shfl_xor_sync(~0u, rs0, 2);
            rs1 += __shfl_xor_sync(~0u, rs1, 1);
            rs1 += __shfl_xor_sync(~0u, rs1, 2);
            l0 = l0*sc0 + rs0;
            l1 = l1*sc1 + rs1;
            #pragma unroll
            for (int j = 0; j < 8; j++) {
                o_[j][0] *= sc0; o_[j][1] *= sc0;
                o_[j][2] *= sc1; o_[j][3] *= sc1;
            }

            #pragma unroll
            for (int j = 0; j < 2; j++) {
                Pw[gid*20     + j*8 + 2*tg]     = __uint_as_float(f2tfr(s[j][0]));
                Pw[gid*20     + j*8 + 2*tg + 1] = __uint_as_float(f2tfr(s[j][1]));
                Pw[(gid+8)*20 + j*8 + 2*tg]     = __uint_as_float(f2tfr(s[j][2]));
                Pw[(gid+8)*20 + j*8 + 2*tg + 1] = __uint_as_float(f2tfr(s[j][3]));
            }
            __syncwarp();
            #pragma unroll
            for (int kk = 0; kk < 2; kk++) {
                uint32_t ap[4];
                ap[0] = __float_as_uint(Pw[gid*20     + kk*8 + tg]);
                ap[1] = __float_as_uint(Pw[(gid+8)*20 + kk*8 + tg]);
                ap[2] = __float_as_uint(Pw[gid*20     + kk*8 + tg + 4]);
                ap[3] = __float_as_uint(Pw[(gid+8)*20 + kk*8 + tg + 4]);
                #pragma unroll
                for (int j = 0; j < 8; j++) {
                    uint32_t bv[2];
                    const float* vr = Vt + (j*8 + gid)*VLD + n0 + kk*8;
                    bv[0] = __float_as_uint(vr[tg]);
                    bv[1] = __float_as_uint(vr[tg + 4]);
                    mma1688_tf32(o_[j], ap, bv);
                }
            }
            __syncwarp();
        }

        float inv0 = 1.f / l0, inv1 = 1.f / l1;
        float* or0 = o + (base + m0 + gid)*384 + h*64;
        float* or1 = or0 + 8*384;
        #pragma unroll
        for (int j = 0; j < 8; j++) {
            *(float2*)(or0 + j*8 + 2*tg) = make_float2(o_[j][0]*inv0, o_[j][1]*inv0);
            *(float2*)(or1 + j*8 + 2*tg) = make_float2(o_[j][2]*inv1, o_[j][3]*inv1);
        }
    }
}

#define ATTN_SMEM(N) ((N*68 + 64*(N+4) + 8*16*20)*4)

// ---------------------------------------------------------------------------
// Merged multi-scale conv (one launch; block ranges dispatch the 3 scales)
// ---------------------------------------------------------------------------
template<int KS, int OHW, int POS>
__device__ __forceinline__ void conv_body(
    const float* __restrict__ x, const float* __restrict__ w,
    float* __restrict__ out, int blk)
{
    extern __shared__ float sp[];
    constexpr int PSZ = CHN*KS*KS;
    constexpr int NPB = (OHW*OHW + POS - 1) / POS;
    const int b = blk / NPB;
    const int pos0 = (blk % NPB) * POS;

    #pragma unroll
    for (int q = 0; q < POS; q++) {
        int pos = pos0 + q;
        if (pos >= OHW*OHW) break;
        int oy = pos / OHW, ox = pos % OHW;
        const float* xb = x + ((size_t)(b*CHN))*HX*HX + (size_t)oy*KS*HX + ox*KS;
        for (int p = threadIdx.x; p < PSZ; p += 256) {
            int ci = p / (KS*KS); int pp = p % (KS*KS);
            int ky = pp / KS, kx = pp % KS;
            sp[q*PSZ + p] = xb[((size_t)ci*HX + ky)*HX + kx];
        }
    }
    __syncthreads();

    const int co = threadIdx.x >> 4, ln = threadIdx.x & 15;
    const float* wp = w + (size_t)co * PSZ;
    float acc[POS];
    #pragma unroll
    for (int q = 0; q < POS; q++) acc[q] = 0.f;

    for (int p = ln; p < PSZ; p += 16) {
        float wv = wp[p];
        #pragma unroll
        for (int q = 0; q < POS; q++)
            acc[q] = fmaf(sp[q*PSZ + p], wv, acc[q]);
    }

    #pragma unroll
    for (int q = 0; q < POS; q++) {
        float a = acc[q];
        #pragma unroll
        for (int off = 8; off; off >>= 1)
            a += __shfl_xor_sync(0xffffffffu, a, off, 16);
        int pos = pos0 + q;
        if (ln == 0 && pos < OHW*OHW)
            out[(size_t)(b*CHN+co)*OHW*OHW + pos] = a;
    }
}

__global__ void __launch_bounds__(256) conv_all_kernel(
    const float* __restrict__ x, const float* __restrict__ cs18,
    const float* __restrict__ cs16, const float* __restrict__ cs14)
{
    int blk = blockIdx.x;
    if (blk < 16*28)           conv_body<18,14,7>(x, cs18, g_conv18, blk);
    else if (blk < 16*28+16*32) conv_body<16,16,8>(x, cs16, g_conv16, blk - 16*28);
    else                        conv_body<14,18,9>(x, cs14, g_conv14, blk - 16*28 - 16*32);
}
#define CONV_ALL_SMEM (7*CHN*18*18*4)
#define CONV_ALL_GRID (16*28 + 16*32 + 16*36)

// ---------------------------------------------------------------------------
// Merged pool + gram + per-batch argsort (one block per batch)
// ---------------------------------------------------------------------------
__global__ void __launch_bounds__(256) pool_gram_sort_kernel(
    const float* __restrict__ W, float* __restrict__ out_vals, float* __restrict__ out_idx)
{
    __shared__ float tok[77*16];
    __shared__ float ms[77*16];
    __shared__ float cm[256];
    __shared__ float nrm[16];
    __shared__ float wv[16];
    int b = blockIdx.x, tid = threadIdx.x;

    for (int i = tid; i < 77*16; i += 256) {
        int c = i & 15, l = i >> 4;
        float av = 0.f, mx = -1e30f;
        if (l < 16) {
            int li = l, py = li/4, px = li%4;
            const float* cb = g_conv18 + (size_t)(b*16+c)*14*14;
            for (int ky=0; ky<3; ky++) for (int kx=0; kx<3; kx++) {
                float v = cb[(py*3+ky)*14 + (px*3+kx)];
                av += v; mx = fmaxf(mx, v);
            }
        } else if (l < 41) {
            int li = l-16, py = li/5, px = li%5;
            const float* cb = g_conv16 + (size_t)(b*16+c)*16*16;
            for (int ky=0; ky<3; ky++) for (int kx=0; kx<3; kx++) {
                float v = cb[(py*3+ky)*16 + (px*3+kx)];
                av += v; mx = fmaxf(mx, v);
            }
        } else {
            int li = l-41, py = li/6, px = li%6;
            const float* cb = g_conv14 + (size_t)(b*16+c)*18*18;
            for (int ky=0; ky<3; ky++) for (int kx=0; kx<3; kx++) {
                float v = cb[(py*3+ky)*18 + (px*3+kx)];
                av += v; mx = fmaxf(mx, v);
            }
        }
        tok[i] = av*(1.f/9.f) + mx;
    }
    __syncthreads();

    for (int i = tid; i < 77*16; i += 256) {
        int l = i >> 4, d = i & 15;
        float s = 0.f;
        #pragma unroll
        for (int c = 0; c < 16; c++) s += tok[l*16+c] * W[c*16+d];
        ms[i] = s;
    }
    __syncthreads();
    {
        int c = tid >> 4, d = tid & 15;
        float s = 0.f;
        for (int l = 0; l < 77; l++) s += ms[l*16+c] * ms[l*16+d];
        cm[tid] = (c == d) ? 0.f : s;
    }
    __syncthreads();
    if (tid < 16) {
        float s = 0.f;
        #pragma unroll
        for (int d = 0; d < 16; d++) { float v = cm[tid*16+d]; s += v*v; }
        nrm[tid] = fmaxf(sqrtf(s), 1e-12f);
    }
    __syncthreads();
    float v = cm[tid] / nrm[tid >> 4];
    __syncthreads();
    cm[tid] = v;
    __syncthreads();
    if (tid < 16) {
        float s = 0.f;
        #pragma unroll
        for (int d = 0; d < 16; d++) s += fabsf(cm[tid*16+d]);
        g_wbuf[b*16 + tid] = s;
        wv[tid] = s;
    }
    __syncthreads();

    if (tid == 0) {
        float vv[16]; int id[16];
        for (int i = 0; i < 16; i++) { vv[i] = wv[i]; id[i] = i; }
        for (int i = 1; i < 16; i++) {
            float kv = vv[i]; int ki = id[i]; int j = i-1;
            while (j >= 0 && vv[j] < kv) { vv[j+1]=vv[j]; id[j+1]=id[j]; j--; }
            vv[j+1]=kv; id[j+1]=ki;
        }
        for (int i = 0; i < 16; i++) {
            g_order[b*16+i] = id[i];
            out_vals[b*16+i] = vv[i];
            out_idx[b*16+i]  = (float)id[i];
        }
    }
}

// ---------------------------------------------------------------------------
// Merged prep: im2col(z) + im2col(x) + patchw transpose
// ---------------------------------------------------------------------------
#define ZCOLT (NGRP*BB*NTZ*768)
#define XCOLT (NGRP*BB*NTX*768)
#define PWT   (384*768)
#define PREP_TOTAL (ZCOLT + XCOLT + PWT)

__device__ __forceinline__ void im2col_one(
    const float* __restrict__ img, float* __restrict__ A,
    int idx, int NT, int PW, int HW, int rowOff)
{
    int k = idx % 768; int m = idx / 768;
    int n = m % NT; int gb = m / NT;
    int b = gb & 15; int g = gb >> 4;
    int c = k >> 8; int rr = k & 255;
    int ky = rr >> 4, kx = rr & 15;
    int ch = g_order[b*16 + 3*g + c];
    int py = n / PW, px = n % PW;
    float mean, inv;
    if (c == 0)      { mean = 0.485f; inv = 1.f/0.229f; }
    else if (c == 1) { mean = 0.456f; inv = 1.f/0.224f; }
    else             { mean = 0.406f; inv = 1.f/0.225f; }
    float v = img[((size_t)(b*CHN+ch)*HW + py*16+ky)*HW + px*16+kx];
    size_t row = (size_t)gb*NTOT + rowOff + n;
    A[row*768 + k] = (v - mean) * inv;
}

__global__ void prep_kernel(const float* __restrict__ z, const float* __restrict__ x,
                            const float* __restrict__ patchw, float* __restrict__ col)
{
    int idx = blockIdx.x*256 + threadIdx.x;
    if (idx < ZCOLT) {
        im2col_one(z, col, idx, NTZ, 8, HZ, 0);
    } else if (idx < ZCOLT + XCOLT) {
        im2col_one(x, col, idx - ZCOLT, NTX, 16, HX, NTZ);
    } else if (idx < PREP_TOTAL) {
        int i = idx - ZCOLT - XCOLT;
        int nrow = i / 768, k = i % 768;
        g_patchw_t[k*384 + nrow] = patchw[i];
    }
}

// ---------------------------------------------------------------------------
// Merged flat + channel-scaled copies for z AND x (float4, range dispatch)
// ---------------------------------------------------------------------------
#define ZQ (BB*CHN*HZ*HZ/4)   // 1,048,576
#define XQ (BB*CHN*HX*HX/4)   // 4,194,304

__global__ void copy_all_kernel(const float* __restrict__ z, const float* __restrict__ x,
                                float* __restrict__ out)
{
    int i4 = blockIdx.x*256 + threadIdx.x;
    if (i4 < ZQ) {
        int bc = i4 / (HZ*HZ/4);
        float w = g_wbuf[bc];
        float4 v = ((const float4*)z)[i4];
        ((float4*)(out + OFF_ZF))[i4] = v;
        ((float4*)(out + OFF_ZCG))[i4] = make_float4(v.x*w, v.y*w, v.z*w, v.w*w);
    } else if (i4 < ZQ + XQ) {
        int j4 = i4 - ZQ;
        int bc = j4 / (HX*HX/4);
        float w = g_wbuf[bc];
        float4 v = ((const float4*)x)[j4];
        ((float4*)(out + OFF_XF))[j4] = v;
        ((float4*)(out + OFF_XCG))[j4] = make_float4(v.x*w, v.y*w, v.z*w, v.w*w);
    }
}

// ---------------------------------------------------------------------------
// LayerNorm over E=384
// ---------------------------------------------------------------------------
__global__ void __launch_bounds__(128) ln_kernel(
    const float* __restrict__ in, float* __restrict__ out,
    const float* __restrict__ s, const float* __restrict__ bb)
{
    int row = blockIdx.x, tid = threadIdx.x;
    const float* ip = in + (size_t)row*384;
    float v0 = ip[tid], v1 = ip[tid+128], v2 = ip[tid+256];
    __shared__ float red[4];
    float loc = v0 + v1 + v2;
    #pragma unroll
    for (int o = 16; o; o >>= 1) loc += __shfl_xor_sync(~0u, loc, o);
    int w = tid >> 5, ln = tid & 31;
    if (ln == 0) red[w] = loc;
    __syncthreads();
    float mu = (red[0]+red[1]+red[2]+red[3]) * (1.f/384.f);
    float d0 = v0-mu, d1 = v1-mu, d2 = v2-mu;
    float loc2 = d0*d0 + d1*d1 + d2*d2;
    #pragma unroll
    for (int o = 16; o; o >>= 1) loc2 += __shfl_xor_sync(~0u, loc2, o);
    __syncthreads();
    if (ln == 0) red[w] = loc2;
    __syncthreads();
    float var = (red[0]+red[1]+red[2]+red[3]) * (1.f/384.f);
    float rs = rsqrtf(var + 1e-6f);
    float* op = out + (size_t)row*384;
    op[tid]     = d0*rs*s[tid]     + bb[tid];
    op[tid+128] = d1*rs*s[tid+128] + bb[tid+128];
    op[tid+256] = d2*rs*s[tid+256] + bb[tid+256];
}

// ---------------------------------------------------------------------------
// group-sum + final LayerNorm
// ---------------------------------------------------------------------------
__global__ void __launch_bounds__(128) final_kernel(
    const float* __restrict__ s, const float* __restrict__ bb, float* __restrict__ out)
{
    int row = blockIdx.x;
    int b = row / NTOT, n = row % NTOT;
    int tid = threadIdx.x;
    float v[3];
    #pragma unroll
    for (int i = 0; i < 3; i++) {
        int e = tid + 128*i;
        float a = 0.f;
        #pragma unroll
        for (int g = 0; g < 5; g++)
            a += g_t[(((size_t)(g*16+b)*NTOT + n)*384) + e];
        v[i] = a;
    }
    __shared__ float red[4];
    float loc = v[0]+v[1]+v[2];
    #pragma unroll
    for (int o = 16; o; o >>= 1) loc += __shfl_xor_sync(~0u, loc, o);
    int w = tid >> 5, ln = tid & 31;
    if (ln == 0) red[w] = loc;
    __syncthreads();
    float mu = (red[0]+red[1]+red[2]+red[3]) * (1.f/384.f);
    float d0 = v[0]-mu, d1 = v[1]-mu, d2 = v[2]-mu;
    float loc2 = d0*d0 + d1*d1 + d2*d2;
    #pragma unroll
    for (int o = 16; o; o >>= 1) loc2 += __shfl_xor_sync(~0u, loc2, o);
    __syncthreads();
    if (ln == 0) red[w] = loc2;
    __syncthreads();
    float var = (red[0]+red[1]+red[2]+red[3]) * (1.f/384.f);
    float rs = rsqrtf(var + 1e-6f);
    float* op = out + (size_t)row*384;
    op[tid]     = d0*rs*s[tid]     + bb[tid];
    op[tid+128] = d1*rs*s[tid+128] + bb[tid+128];
    op[tid+256] = d2*rs*s[tid+256] + bb[tid+256];
}

// ---------------------------------------------------------------------------
// Host side
// ---------------------------------------------------------------------------
static void run_gemm(const float* A, const float* B, const float* aux, float* C,
                     int M, int N, int K, int epi,
                     const float* pz = nullptr, const float* px = nullptr)
{
    dim3 grid(N/128, M/128);
    switch (epi) {
        case 0: gemm_tf32_kernel<0><<<grid,512,GEMM_SMEM_BYTES>>>(A,B,nullptr,C,M,N,K,nullptr,nullptr); break;
        case 1: gemm_tf32_kernel<1><<<grid,512,GEMM_SMEM_BYTES>>>(A,B,aux,C,M,N,K,nullptr,nullptr); break;
        case 2: gemm_tf32_kernel<2><<<grid,512,GEMM_SMEM_BYTES>>>(A,B,nullptr,C,M,N,K,nullptr,nullptr); break;
        case 4: gemm_tf32_kernel<4><<<grid,512,GEMM_SMEM_BYTES>>>(A,B,aux,C,M,N,K,pz,px); break;
        default: gemm_tf32_kernel<3><<<grid,512,GEMM_SMEM_BYTES>>>(A,B,aux,C,M,N,K,nullptr,nullptr); break;
    }
}

static void run_block(float* tptr, int i, int early, int fusePos,
    const float* ln1s, const float* ln1b, const float* qkvw, const float* projw,
    const float* ln2s, const float* ln2b, const float* mlp1w, const float* mlp2w,
    float* hbuf, float* qkvbuf, float* obuf, float* hidbuf,
    const float* posz, const float* posx)
{
    ln_kernel<<<MTOT,128>>>(tptr, hbuf, ln1s + i*384, ln1b + i*384);
    run_gemm(hbuf, qkvw + (size_t)i*384*1152, nullptr, qkvbuf, MTOT, 1152, 384, 0);
    if (early) {
        attn_mma_kernel<64> <<<GBN*NHD,256,ATTN_SMEM(64)>>>(qkvbuf, obuf, 0);
        attn_mma_kernel<256><<<GBN*NHD,256,ATTN_SMEM(256)>>>(qkvbuf, obuf, NTZ);
    } else {
        attn_mma_kernel<320><<<GBN*NHD,256,ATTN_SMEM(320)>>>(qkvbuf, obuf, 0);
    }
    run_gemm(obuf, projw + (size_t)i*384*384, tptr, tptr, MTOT, 384, 384, 3);
    ln_kernel<<<MTOT,128>>>(tptr, hbuf, ln2s + i*384, ln2b + i*384);
    run_gemm(hbuf, mlp1w + (size_t)i*384*1536, nullptr, hidbuf, MTOT, 1536, 384, 2);
    if (fusePos)
        run_gemm(hidbuf, mlp2w + (size_t)i*1536*384, tptr, tptr, MTOT, 384, 1536, 4, posz, posx);
    else
        run_gemm(hidbuf, mlp2w + (size_t)i*1536*384, tptr, tptr, MTOT, 384, 1536, 3);
}

extern "C" void kernel_launch(void* const* d_in, const int* in_sizes, int n_in,
                              void* d_out, int out_size)
{
    const float* z      = (const float*)d_in[0];
    const float* x      = (const float*)d_in[1];
    const float* cs18   = (const float*)d_in[2];
    const float* cs16   = (const float*)d_in[3];
    const float* cs14   = (const float*)d_in[4];
    const float* csMP   = (const float*)d_in[5];
    const float* patchw = (const float*)d_in[6];
    const float* patchb = (const float*)d_in[7];
    const float* posz   = (const float*)d_in[8];
    const float* posx   = (const float*)d_in[9];
    const float* ln1s   = (const float*)d_in[10];
    const float* ln1b   = (const float*)d_in[11];
    const float* qkvw   = (const float*)d_in[12];
    const float* projw  = (const float*)d_in[13];
    const float* ln2s   = (const float*)d_in[14];
    const float* ln2b   = (const float*)d_in[15];
    const float* mlp1w  = (const float*)d_in[16];
    const float* mlp2w  = (const float*)d_in[17];
    const float* norms  = (const float*)d_in[18];
    const float* normb  = (const float*)d_in[19];
    float* out = (float*)d_out;

    float *p_t, *p_qkv, *p_h, *p_o, *p_hid, *p_col, *p_patchw_t;
    cudaGetSymbolAddress((void**)&p_t, g_t);
    cudaGetSymbolAddress((void**)&p_qkv, g_qkv);
    cudaGetSymbolAddress((void**)&p_h, g_h);
    cudaGetSymbolAddress((void**)&p_o, g_o);
    cudaGetSymbolAddress((void**)&p_hid, g_hidden);
    cudaGetSymbolAddress((void**)&p_col, g_col);
    cudaGetSymbolAddress((void**)&p_patchw_t, g_patchw_t);

    cudaFuncSetAttribute(attn_mma_kernel<64>,  cudaFuncAttributeMaxDynamicSharedMemorySize, ATTN_SMEM(64));
    cudaFuncSetAttribute(attn_mma_kernel<256>, cudaFuncAttributeMaxDynamicSharedMemorySize, ATTN_SMEM(256));
    cudaFuncSetAttribute(attn_mma_kernel<320>, cudaFuncAttributeMaxDynamicSharedMemorySize, ATTN_SMEM(320));
    cudaFuncSetAttribute(gemm_tf32_kernel<0>, cudaFuncAttributeMaxDynamicSharedMemorySize, GEMM_SMEM_BYTES);
    cudaFuncSetAttribute(gemm_tf32_kernel<1>, cudaFuncAttributeMaxDynamicSharedMemorySize, GEMM_SMEM_BYTES);
    cudaFuncSetAttribute(gemm_tf32_kernel<2>, cudaFuncAttributeMaxDynamicSharedMemorySize, GEMM_SMEM_BYTES);
    cudaFuncSetAttribute(gemm_tf32_kernel<3>, cudaFuncAttributeMaxDynamicSharedMemorySize, GEMM_SMEM_BYTES);
    cudaFuncSetAttribute(gemm_tf32_kernel<4>, cudaFuncAttributeMaxDynamicSharedMemorySize, GEMM_SMEM_BYTES);
    cudaFuncSetAttribute(conv_all_kernel, cudaFuncAttributeMaxDynamicSharedMemorySize, CONV_ALL_SMEM);

    // launch 1: merged multi-scale convs
    conv_all_kernel<<<CONV_ALL_GRID,256,CONV_ALL_SMEM>>>(x, cs18, cs16, cs14);
    // launch 2: pool + gram + per-batch argsort
    pool_gram_sort_kernel<<<16,256>>>(csMP, out + OFF_OV, out + OFF_OI);
    // launch 3: im2col z + im2col x + patch weight transpose
    prep_kernel<<<PREP_TOTAL/256,256>>>(z, x, patchw, p_col);
    // launch 4: patch-embed GEMM (profiled slot)
    run_gemm(p_col, p_patchw_t, patchb, p_t, MTOT, 384, 768, 1);

    // merged flat + channel-scaled copies for z and x
    copy_all_kernel<<<(ZQ + XQ + 255)/256, 256>>>(z, x, out);

    // early transformer blocks (segment-local attention); block 1 fuses +pos
    run_block(p_t, 0, 1, 0, ln1s, ln1b, qkvw, projw, ln2s, ln2b,
              mlp1w, mlp2w, p_h, p_qkv, p_o, p_hid, posz, posx);
    run_block(p_t, 1, 1, 1, ln1s, ln1b, qkvw, projw, ln2s, ln2b,
              mlp1w, mlp2w, p_h, p_qkv, p_o, p_hid, posz, posx);

    // late blocks (full attention)
    for (int i = 2; i < 4; i++)
        run_block(p_t, i, 0, 0, ln1s, ln1b, qkvw, projw, ln2s, ln2b,
                  mlp1w, mlp2w, p_h, p_qkv, p_o, p_hid, posz, posx);

    // group-sum + final LayerNorm
    final_kernel<<<16*NTOT, 128>>>(norms, normb, out + OFF_OUT);
}